// round 2
// baseline (speedup 1.0000x reference)
#include <cuda_runtime.h>
#include <math.h>
#include <math_constants.h>

#define B_  2
#define T_  2048
#define C_  1024
#define H_  16
#define D_  64

typedef unsigned long long ull;

// ---- packed f32x2 helpers (sm_103a FFMA2 path, PTX-only) ---------------------
union F2U { float2 f; ull u; };
__device__ __forceinline__ ull pack2(float x, float y) {
    F2U t; t.f = make_float2(x, y); return t.u;
}
__device__ __forceinline__ float2 unpack2(ull v) { F2U t; t.u = v; return t.f; }
__device__ __forceinline__ ull splat2(float x) {
    ull r; asm("mov.b64 %0, {%1, %1};" : "=l"(r) : "f"(x)); return r;
}
__device__ __forceinline__ ull ffma2(ull a, ull b, ull c) {
    ull d; asm("fma.rn.f32x2 %0, %1, %2, %3;" : "=l"(d) : "l"(a), "l"(b), "l"(c));
    return d;
}
__device__ __forceinline__ ull fmul2(ull a, ull b) {
    ull d; asm("mul.rn.f32x2 %0, %1, %2;" : "=l"(d) : "l"(a), "l"(b));
    return d;
}

// Scratch (allocation-free rule: __device__ globals)
static __device__ float g_q[(size_t)B_*H_*T_*D_];
static __device__ float g_k[(size_t)B_*H_*T_*D_];
static __device__ float g_v[(size_t)B_*H_*T_*D_];
static __device__ float g_y[(size_t)B_*T_*C_];
static __device__ float g_bias[H_*T_];     // bias per (head, distance)
static __device__ float g_cos[T_*D_];
static __device__ float g_sin[T_*D_];

// ---------------------------------------------------------------------------
// Tables: rotary cos/sin [T, D] and relative-position bias per distance [H, T]
// ---------------------------------------------------------------------------
__global__ void tables_kernel(const float* __restrict__ rel_table) {
    int idx = blockIdx.x * blockDim.x + threadIdx.x;
    if (idx < T_ * D_) {
        int t = idx >> 6;
        int d = idx & 63;
        int j = d & 31;                       // freqs duplicated across halves
        float inv = (float)pow(10000.0, -(double)(2 * j) / 64.0);
        float fr = (float)t * inv;
        g_cos[idx] = cosf(fr);
        g_sin[idx] = sinf(fr);
    }
    if (idx < H_ * T_) {
        int h = idx / T_;
        int n = idx % T_;                     // distance = q_pos - k_pos >= 0
        int bucket;
        if (n < 16) {
            bucket = n;
        } else {
            float v = logf((float)n * (1.0f / 16.0f)) / 2.0794415416798357f * 16.0f;
            bucket = 16 + (int)v;             // trunc toward zero, v >= 0
            if (bucket > 31) bucket = 31;
        }
        g_bias[idx] = rel_table[bucket * H_ + h];
    }
}

// ---------------------------------------------------------------------------
// 128x128x16 tiled SGEMM body, FFMA2 inner product. M=B*T=4096, N=K=C=1024.
// mode 0: out[m*N+n]  (row-major [B*T, C])
// mode 1: out in head layout [B,H,T,D]
// ---------------------------------------------------------------------------
__device__ __forceinline__ void gemm_body(const float* __restrict__ A,
                                          const float* __restrict__ W,
                                          const float* __restrict__ bias,
                                          float* __restrict__ out,
                                          int mode) {
    __shared__ float As[16][128];
    __shared__ float Ws[16][132];

    const int K = C_, N = C_;
    int tid = threadIdx.x;
    int bm = blockIdx.y * 128;
    int bn = blockIdx.x * 128;
    int ty = tid >> 4;     // 0..15
    int tx = tid & 15;     // 0..15

    ull acc2[8][4];
#pragma unroll
    for (int i = 0; i < 8; i++)
#pragma unroll
        for (int j = 0; j < 4; j++) acc2[i][j] = 0ull;

    int arow = tid >> 2;            // 0..63
    int ac4  = (tid & 3) << 2;      // 0,4,8,12
    int wrow = tid >> 5;            // 0..7
    int wc4  = (tid & 31) << 2;     // 0..124

    for (int k0 = 0; k0 < K; k0 += 16) {
        float4 a0 = *(const float4*)(A + (size_t)(bm + arow) * K + k0 + ac4);
        float4 a1 = *(const float4*)(A + (size_t)(bm + arow + 64) * K + k0 + ac4);
        float4 w0 = *(const float4*)(W + (size_t)(k0 + wrow) * N + bn + wc4);
        float4 w1 = *(const float4*)(W + (size_t)(k0 + wrow + 8) * N + bn + wc4);

        __syncthreads();
        As[ac4 + 0][arow] = a0.x; As[ac4 + 1][arow] = a0.y;
        As[ac4 + 2][arow] = a0.z; As[ac4 + 3][arow] = a0.w;
        As[ac4 + 0][arow + 64] = a1.x; As[ac4 + 1][arow + 64] = a1.y;
        As[ac4 + 2][arow + 64] = a1.z; As[ac4 + 3][arow + 64] = a1.w;
        *(float4*)&Ws[wrow][wc4]     = w0;
        *(float4*)&Ws[wrow + 8][wc4] = w1;
        __syncthreads();

#pragma unroll
        for (int kk = 0; kk < 16; kk++) {
            float4 av0 = *(const float4*)&As[kk][ty * 8];
            float4 av1 = *(const float4*)&As[kk][ty * 8 + 4];
            float4 wv0 = *(const float4*)&Ws[kk][tx * 8];
            float4 wv1 = *(const float4*)&Ws[kk][tx * 8 + 4];
            ull b[4];
            b[0] = pack2(wv0.x, wv0.y); b[1] = pack2(wv0.z, wv0.w);
            b[2] = pack2(wv1.x, wv1.y); b[3] = pack2(wv1.z, wv1.w);
            ull av[8];
            av[0] = splat2(av0.x); av[1] = splat2(av0.y);
            av[2] = splat2(av0.z); av[3] = splat2(av0.w);
            av[4] = splat2(av1.x); av[5] = splat2(av1.y);
            av[6] = splat2(av1.z); av[7] = splat2(av1.w);
#pragma unroll
            for (int i = 0; i < 8; i++)
#pragma unroll
                for (int j = 0; j < 4; j++)
                    acc2[i][j] = ffma2(av[i], b[j], acc2[i][j]);
        }
    }

    int gcol0 = bn + tx * 8;
    float bv[8];
#pragma unroll
    for (int j = 0; j < 8; j++) bv[j] = bias[gcol0 + j];

    if (mode == 0) {
#pragma unroll
        for (int i = 0; i < 8; i++) {
            int grow = bm + ty * 8 + i;
            float* op = out + (size_t)grow * N + gcol0;
#pragma unroll
            for (int j = 0; j < 4; j++) {
                float2 p = unpack2(acc2[i][j]);
                op[j * 2 + 0] = p.x + bv[j * 2 + 0];
                op[j * 2 + 1] = p.y + bv[j * 2 + 1];
            }
        }
    } else {
        int h  = gcol0 >> 6;
        int d0 = gcol0 & 63;
#pragma unroll
        for (int i = 0; i < 8; i++) {
            int grow = bm + ty * 8 + i;
            int b = grow >> 11;
            int t = grow & (T_ - 1);
            float* dp = out + (((size_t)b * H_ + h) * T_ + t) * D_ + d0;
#pragma unroll
            for (int j = 0; j < 4; j++) {
                float2 p = unpack2(acc2[i][j]);
                dp[j * 2 + 0] = p.x + bv[j * 2 + 0];
                dp[j * 2 + 1] = p.y + bv[j * 2 + 1];
            }
        }
    }
}

__global__ __launch_bounds__(256) void qkv_gemm_kernel(
        const float* __restrict__ x,
        const float* __restrict__ Wq, const float* __restrict__ bq,
        const float* __restrict__ Wk, const float* __restrict__ bk,
        const float* __restrict__ Wv, const float* __restrict__ bv) {
    const float* W; const float* bias; float* dst;
    int z = blockIdx.z;
    if (z == 0)      { W = Wq; bias = bq; dst = g_q; }
    else if (z == 1) { W = Wk; bias = bk; dst = g_k; }
    else             { W = Wv; bias = bv; dst = g_v; }
    gemm_body(x, W, bias, dst, 1);
}

__global__ __launch_bounds__(256) void proj_gemm_kernel(
        const float* __restrict__ Wp, const float* __restrict__ bp,
        float* __restrict__ out) {
    gemm_body(g_y, Wp, bp, out, 0);
}

// ---------------------------------------------------------------------------
// Rotary: each thread handles the (d, d+32) pair -> no cross-thread race.
// ---------------------------------------------------------------------------
__global__ void rope_kernel() {
    const int NH = B_ * H_ * T_ * 32;
    int idx = blockIdx.x * blockDim.x + threadIdx.x;
    float* arr = g_q;
    if (idx >= NH) { arr = g_k; idx -= NH; }
    if (idx >= NH) return;
    int d = idx & 31;
    int row = idx >> 5;                 // (b*H+h)*T + t
    int t = row & (T_ - 1);
    float c = g_cos[(t << 6) + d];
    float s = g_sin[(t << 6) + d];
    size_t p = ((size_t)row << 6) + d;
    float x1 = arr[p], x2 = arr[p + 32];
    arr[p]      = x1 * c - x2 * s;
    arr[p + 32] = x2 * c + x1 * s;
}

// ---------------------------------------------------------------------------
// Flash-style causal attention. 128 queries / CTA, 1 query / thread.
// Chunk-wise online softmax (16 keys per chunk), FFMA2 packed math.
// ---------------------------------------------------------------------------
__global__ __launch_bounds__(128) void attn_kernel() {
    __shared__ float Ks[64 * 64];
    __shared__ float Vs[64 * 64];

    int bh = blockIdx.y;                  // b*H + h
    int h = bh & (H_ - 1);
    int qb = gridDim.x - 1 - blockIdx.x;  // big-work CTAs launch first
    int q0 = qb << 7;                     // 128 queries per CTA
    int tid = threadIdx.x;
    int qi = q0 + tid;

    const float* kbase = g_k + (size_t)bh * T_ * D_;
    const float* vbase = g_v + (size_t)bh * T_ * D_;
    const float* brow  = g_bias + h * T_;

    // load + pre-scale Q (scale by 1/sqrt(D) up front)
    ull qreg2[32];
    {
        const float2* qp = (const float2*)(g_q + ((size_t)bh * T_ + qi) * D_);
#pragma unroll
        for (int i = 0; i < 32; i++) {
            float2 v = qp[i];
            qreg2[i] = pack2(v.x * 0.125f, v.y * 0.125f);
        }
    }

    float mval = -CUDART_INF_F;
    float lval = 0.f;
    ull acc2[32];
#pragma unroll
    for (int d = 0; d < 32; d++) acc2[d] = 0ull;

    int jend = q0 + 128;
    for (int j0 = 0; j0 < jend; j0 += 64) {
        __syncthreads();
        const float4* k4 = (const float4*)(kbase + (size_t)j0 * D_);
        const float4* v4 = (const float4*)(vbase + (size_t)j0 * D_);
#pragma unroll
        for (int i = tid; i < 1024; i += 128) {
            ((float4*)Ks)[i] = k4[i];
            ((float4*)Vs)[i] = v4[i];
        }
        __syncthreads();

        int rem = qi - j0;                 // last valid local key index
#pragma unroll 1
        for (int c = 0; c < 4; c++) {
            if (c * 16 > rem) break;
            float s[16];
#pragma unroll
            for (int jj = 0; jj < 16; jj++) {
                int j = c * 16 + jj;
                const ull* kr = (const ull*)(Ks + j * 64);
                ull d0 = 0ull, d1 = 0ull, d2 = 0ull, d3 = 0ull;
#pragma unroll
                for (int d = 0; d < 8; d++) {
                    d0 = ffma2(qreg2[d],      kr[d],      d0);
                    d1 = ffma2(qreg2[8 + d],  kr[8 + d],  d1);
                    d2 = ffma2(qreg2[16 + d], kr[16 + d], d2);
                    d3 = ffma2(qreg2[24 + d], kr[24 + d], d3);
                }
                float2 e0 = unpack2(d0), e1 = unpack2(d1);
                float2 e2 = unpack2(d2), e3 = unpack2(d3);
                float dot = (e0.x + e0.y) + (e1.x + e1.y)
                          + (e2.x + e2.y) + (e3.x + e3.y);
                int dist = rem - j;
                int bidx = dist > 0 ? dist : 0;
                float val = dot + 0.125f * __ldg(brow + bidx);
                s[jj] = (dist >= 0) ? val : -CUDART_INF_F;
            }
            // chunk max (tree)
            float m01, m23;
            {
                float a0 = fmaxf(s[0], s[1]),   a1 = fmaxf(s[2], s[3]);
                float a2 = fmaxf(s[4], s[5]),   a3 = fmaxf(s[6], s[7]);
                float a4 = fmaxf(s[8], s[9]),   a5 = fmaxf(s[10], s[11]);
                float a6 = fmaxf(s[12], s[13]), a7 = fmaxf(s[14], s[15]);
                m01 = fmaxf(fmaxf(a0, a1), fmaxf(a2, a3));
                m23 = fmaxf(fmaxf(a4, a5), fmaxf(a6, a7));
            }
            float cm = fmaxf(m01, m23);
            if (cm > mval) {
                float corr = __expf(mval - cm);   // 0 on first hit
                mval = cm;
                lval *= corr;
                ull corr2 = splat2(corr);
#pragma unroll
                for (int d = 0; d < 32; d++) acc2[d] = fmul2(acc2[d], corr2);
            }
#pragma unroll
            for (int jj = 0; jj < 16; jj++) {
                s[jj] = __expf(s[jj] - mval);      // masked -> 0
                lval += s[jj];
            }
#pragma unroll
            for (int jj = 0; jj < 16; jj++) {
                ull p2 = splat2(s[jj]);
                const ull* vr = (const ull*)(Vs + (c * 16 + jj) * 64);
#pragma unroll
                for (int d = 0; d < 32; d++)
                    acc2[d] = ffma2(p2, vr[d], acc2[d]);
            }
        }
    }

    float inv = 1.f / lval;
    int b = bh >> 4;
    float* yo = g_y + ((size_t)b * T_ + qi) * C_ + h * D_;
#pragma unroll
    for (int d4 = 0; d4 < 16; d4++) {
        float2 p0 = unpack2(acc2[d4 * 2 + 0]);
        float2 p1 = unpack2(acc2[d4 * 2 + 1]);
        float4 o;
        o.x = p0.x * inv; o.y = p0.y * inv;
        o.z = p1.x * inv; o.w = p1.y * inv;
        ((float4*)yo)[d4] = o;
    }
}

// ---------------------------------------------------------------------------
extern "C" void kernel_launch(void* const* d_in, const int* in_sizes, int n_in,
                              void* d_out, int out_size) {
    const float* x   = (const float*)d_in[0];
    const float* Wq  = (const float*)d_in[1];
    const float* bq  = (const float*)d_in[2];
    const float* Wk  = (const float*)d_in[3];
    const float* bk  = (const float*)d_in[4];
    const float* Wv  = (const float*)d_in[5];
    const float* bv  = (const float*)d_in[6];
    const float* Wp  = (const float*)d_in[7];
    const float* bp  = (const float*)d_in[8];
    const float* tbl = (const float*)d_in[9];
    float* out = (float*)d_out;

    tables_kernel<<<(T_ * D_ + 255) / 256, 256>>>(tbl);

    dim3 ggrid(C_ / 128, (B_ * T_) / 128, 3);
    qkv_gemm_kernel<<<ggrid, 256>>>(x, Wq, bq, Wk, bk, Wv, bv);

    int rope_threads = 2 * B_ * H_ * T_ * 32;
    rope_kernel<<<(rope_threads + 255) / 256, 256>>>();

    attn_kernel<<<dim3(T_ / 128, B_ * H_), 128>>>();

    proj_gemm_kernel<<<dim3(C_ / 128, (B_ * T_) / 128), 256>>>(Wp, bp, out);
}

// round 4
// speedup vs baseline: 1.4820x; 1.4820x over previous
#include <cuda_runtime.h>
#include <cuda_bf16.h>
#include <math.h>
#include <math_constants.h>

#define B_  2
#define T_  2048
#define C_  1024
#define H_  16
#define D_  64
#define KCH 32               // K elems per pipeline chunk
#define NCH (C_ / KCH)       // 32 chunks

typedef unsigned int u32;

// ---------------------------------------------------------------------------
// Scratch (__device__ globals: allocation-free rule)
// ---------------------------------------------------------------------------
static __device__ float g_q[(size_t)B_*H_*T_*D_];
static __device__ float g_k[(size_t)B_*H_*T_*D_];
static __device__ float g_v[(size_t)B_*H_*T_*D_];
static __device__ float g_y[(size_t)B_*T_*C_];
static __device__ float g_bias[H_*T_];
static __device__ float g_cos[T_*D_];
static __device__ float g_sin[T_*D_];
// bf16 hi/lo operands
static __device__ __nv_bfloat16 g_xh[(size_t)B_*T_*C_];
static __device__ __nv_bfloat16 g_xl[(size_t)B_*T_*C_];
static __device__ __nv_bfloat16 g_yh[(size_t)B_*T_*C_];
static __device__ __nv_bfloat16 g_yl[(size_t)B_*T_*C_];
static __device__ __nv_bfloat16 g_wh[4 * (size_t)C_*C_];   // W hi (orig [K,N] layout)
static __device__ __nv_bfloat16 g_wl[4 * (size_t)C_*C_];   // W lo

// ---------------------------------------------------------------------------
// Baseline-PTX helpers (sm_80-compatible: ldmatrix / mma.sync / cp.async)
// ---------------------------------------------------------------------------
__device__ __forceinline__ u32 smem_u32(const void* p) {
    u32 a;
    asm("{ .reg .u64 t; cvta.to.shared.u64 t, %1; cvt.u32.u64 %0, t; }" : "=r"(a) : "l"(p));
    return a;
}
__device__ __forceinline__ void ldsm_x4(u32 addr, u32& r0, u32& r1, u32& r2, u32& r3) {
    asm volatile("ldmatrix.sync.aligned.m8n8.x4.shared.b16 {%0,%1,%2,%3}, [%4];"
                 : "=r"(r0), "=r"(r1), "=r"(r2), "=r"(r3) : "r"(addr));
}
__device__ __forceinline__ void ldsm_x4_t(u32 addr, u32& r0, u32& r1, u32& r2, u32& r3) {
    asm volatile("ldmatrix.sync.aligned.m8n8.x4.trans.shared.b16 {%0,%1,%2,%3}, [%4];"
                 : "=r"(r0), "=r"(r1), "=r"(r2), "=r"(r3) : "r"(addr));
}
__device__ __forceinline__ void mma_bf16(float* c, u32 a0, u32 a1, u32 a2, u32 a3,
                                         u32 b0, u32 b1) {
    asm volatile("mma.sync.aligned.m16n8k16.row.col.f32.bf16.bf16.f32 "
                 "{%0,%1,%2,%3}, {%4,%5,%6,%7}, {%8,%9}, {%0,%1,%2,%3};"
                 : "+f"(c[0]), "+f"(c[1]), "+f"(c[2]), "+f"(c[3])
                 : "r"(a0), "r"(a1), "r"(a2), "r"(a3), "r"(b0), "r"(b1));
}
#define CP_ASYNC16(dst, src) \
    asm volatile("cp.async.cg.shared.global [%0], [%1], 16;" :: "r"(dst), "l"(src))
#define CP_COMMIT() asm volatile("cp.async.commit_group;" ::: "memory")
#define CP_WAIT1()  asm volatile("cp.async.wait_group 1;" ::: "memory")
#define CP_WAIT0()  asm volatile("cp.async.wait_group 0;" ::: "memory")

// ---------------------------------------------------------------------------
// Tables
// ---------------------------------------------------------------------------
__global__ void tables_kernel(const float* __restrict__ rel_table) {
    int idx = blockIdx.x * blockDim.x + threadIdx.x;
    if (idx < T_ * D_) {
        int t = idx >> 6;
        int d = idx & 63;
        int j = d & 31;
        float inv = (float)pow(10000.0, -(double)(2 * j) / 64.0);
        float fr = (float)t * inv;
        g_cos[idx] = cosf(fr);
        g_sin[idx] = sinf(fr);
    }
    if (idx < H_ * T_) {
        int h = idx / T_;
        int n = idx % T_;
        int bucket;
        if (n < 16) {
            bucket = n;
        } else {
            float v = logf((float)n * (1.0f / 16.0f)) / 2.0794415416798357f * 16.0f;
            bucket = 16 + (int)v;
            if (bucket > 31) bucket = 31;
        }
        g_bias[idx] = rel_table[bucket * H_ + h];
    }
}

// ---------------------------------------------------------------------------
// fp32 -> bf16 hi/lo splits
// ---------------------------------------------------------------------------
__device__ __forceinline__ void split1(float v, __nv_bfloat16& h, __nv_bfloat16& l) {
    h = __float2bfloat16(v);
    l = __float2bfloat16(v - __bfloat162float(h));
}

__global__ void split_act_kernel(const float* __restrict__ xin, int which) {
    const float* src = which == 0 ? xin : g_y;
    __nv_bfloat16* oh = which == 0 ? g_xh : g_yh;
    __nv_bfloat16* ol = which == 0 ? g_xl : g_yl;
    int i = blockIdx.x * 256 + threadIdx.x;      // float4 index
    float4 v = ((const float4*)src)[i];
    __nv_bfloat16 h0, h1, h2, h3, l0, l1, l2, l3;
    split1(v.x, h0, l0); split1(v.y, h1, l1);
    split1(v.z, h2, l2); split1(v.w, h3, l3);
    ((__nv_bfloat162*)oh)[i * 2 + 0] = __nv_bfloat162(h0, h1);
    ((__nv_bfloat162*)oh)[i * 2 + 1] = __nv_bfloat162(h2, h3);
    ((__nv_bfloat162*)ol)[i * 2 + 0] = __nv_bfloat162(l0, l1);
    ((__nv_bfloat162*)ol)[i * 2 + 1] = __nv_bfloat162(l2, l3);
}

__global__ void split_w_kernel(const float* __restrict__ Wq, const float* __restrict__ Wk,
                               const float* __restrict__ Wv, const float* __restrict__ Wp) {
    int z = blockIdx.y;
    const float* W = z == 0 ? Wq : z == 1 ? Wk : z == 2 ? Wv : Wp;
    __nv_bfloat16* oh = g_wh + (size_t)z * C_ * C_;
    __nv_bfloat16* ol = g_wl + (size_t)z * C_ * C_;
    int i = blockIdx.x * 256 + threadIdx.x;      // float4 index (256K per matrix)
    float4 v = ((const float4*)W)[i];
    __nv_bfloat16 h0, h1, h2, h3, l0, l1, l2, l3;
    split1(v.x, h0, l0); split1(v.y, h1, l1);
    split1(v.z, h2, l2); split1(v.w, h3, l3);
    ((__nv_bfloat162*)oh)[i * 2 + 0] = __nv_bfloat162(h0, h1);
    ((__nv_bfloat162*)oh)[i * 2 + 1] = __nv_bfloat162(h2, h3);
    ((__nv_bfloat162*)ol)[i * 2 + 0] = __nv_bfloat162(l0, l1);
    ((__nv_bfloat162*)ol)[i * 2 + 1] = __nv_bfloat162(l2, l3);
}

// ---------------------------------------------------------------------------
// HMMA GEMM: out[4096,1024] = A[4096,1024] @ W[1024,1024] + bias
// A, W as bf16 hi/lo. 128x128 CTA tile, 8 warps (2x4), m16n8k16 fragments,
// 2-stage cp.async pipeline on K chunks of 32.
// mode 0: row-major out; mode 1: head layout [B,H,T,D].
// ---------------------------------------------------------------------------
#define SA 40        // A smem row stride (halves), k-pad
#define SB 136       // B smem row stride (halves), n-pad
#define AH_OFF 0
#define AL_OFF (128 * SA * 2)                     // 10240
#define BH_OFF (AL_OFF + 128 * SA * 2)            // 20480
#define BL_OFF (BH_OFF + KCH * SB * 2)            // 29184
#define STAGE_BYTES (BL_OFF + KCH * SB * 2)       // 37888
#define SMEM_TOTAL (2 * STAGE_BYTES)              // 75776

__device__ __forceinline__ void hmma_gemm_body(
        const __nv_bfloat16* __restrict__ Ah, const __nv_bfloat16* __restrict__ Al,
        const __nv_bfloat16* __restrict__ Wh, const __nv_bfloat16* __restrict__ Wl,
        const float* __restrict__ bias, float* __restrict__ out, int mode) {
    extern __shared__ char smem[];
    u32 sb = smem_u32(smem);

    int tid = threadIdx.x;
    int lane = tid & 31;
    int wid = tid >> 5;
    int wm = wid & 1;         // 0..1 -> 64-row group
    int wn = wid >> 1;        // 0..3 -> 32-col group
    int bm = blockIdx.y * 128;
    int bn = blockIdx.x * 128;

    float acc[4][4][4];
#pragma unroll
    for (int i = 0; i < 4; i++)
#pragma unroll
        for (int j = 0; j < 4; j++)
#pragma unroll
            for (int r = 0; r < 4; r++) acc[i][j][r] = 0.f;

    // cp.async load of chunk c into stage s
    auto load_chunk = [&](int c, int s) {
        u32 st = sb + s * STAGE_BYTES;
        int c0 = c * KCH;
        // A: 128 rows x 32 halves = 512 x 16B per array
#pragma unroll
        for (int u = tid; u < 512; u += 256) {
            int row = u >> 2, seg = u & 3;
            size_t gofs = (size_t)(bm + row) * C_ + c0 + seg * 8;
            u32 dofs = (u32)(row * SA + seg * 8) * 2;
            CP_ASYNC16(st + AH_OFF + dofs, Ah + gofs);
            CP_ASYNC16(st + AL_OFF + dofs, Al + gofs);
        }
        // B: 32 rows x 128 halves = 512 x 16B per array
#pragma unroll
        for (int u = tid; u < 512; u += 256) {
            int row = u >> 4, seg = u & 15;
            size_t gofs = (size_t)(c0 + row) * C_ + bn + seg * 8;
            u32 dofs = (u32)(row * SB + seg * 8) * 2;
            CP_ASYNC16(st + BH_OFF + dofs, Wh + gofs);
            CP_ASYNC16(st + BL_OFF + dofs, Wl + gofs);
        }
        CP_COMMIT();
    };

    load_chunk(0, 0);

    for (int c = 0; c < NCH; c++) {
        int s = c & 1;
        if (c + 1 < NCH) { load_chunk(c + 1, s ^ 1); CP_WAIT1(); }
        else             { CP_WAIT0(); }
        __syncthreads();

        u32 st = sb + s * STAGE_BYTES;
        // ldmatrix lane addressing
        int lr = lane & 15;             // row-within-16
        int lh = lane >> 4;             // 0/1 half select
#pragma unroll
        for (int ks = 0; ks < 2; ks++) {
            int k0 = ks * 16;
            // A fragments: 4 m-tiles, hi & lo
            u32 ah[4][4], al[4][4];
#pragma unroll
            for (int mt = 0; mt < 4; mt++) {
                u32 arow = (u32)(wm * 64 + mt * 16 + lr);
                u32 aoff = (arow * SA + k0 + lh * 8) * 2;
                ldsm_x4(st + AH_OFF + aoff, ah[mt][0], ah[mt][1], ah[mt][2], ah[mt][3]);
                ldsm_x4(st + AL_OFF + aoff, al[mt][0], al[mt][1], al[mt][2], al[mt][3]);
            }
#pragma unroll
            for (int np = 0; np < 2; np++) {
                u32 brow = (u32)(k0 + lr);
                u32 bcol = (u32)(wn * 32 + np * 16 + lh * 8);
                u32 boff = (brow * SB + bcol) * 2;
                u32 bh0, bh1, bh2, bh3, bl0, bl1, bl2, bl3;
                ldsm_x4_t(st + BH_OFF + boff, bh0, bh1, bh2, bh3);
                ldsm_x4_t(st + BL_OFF + boff, bl0, bl1, bl2, bl3);
#pragma unroll
                for (int mt = 0; mt < 4; mt++) {
                    float* c0p = acc[mt][np * 2];
                    float* c1p = acc[mt][np * 2 + 1];
                    mma_bf16(c0p, ah[mt][0], ah[mt][1], ah[mt][2], ah[mt][3], bh0, bh1);
                    mma_bf16(c1p, ah[mt][0], ah[mt][1], ah[mt][2], ah[mt][3], bh2, bh3);
                    mma_bf16(c0p, ah[mt][0], ah[mt][1], ah[mt][2], ah[mt][3], bl0, bl1);
                    mma_bf16(c1p, ah[mt][0], ah[mt][1], ah[mt][2], ah[mt][3], bl2, bl3);
                    mma_bf16(c0p, al[mt][0], al[mt][1], al[mt][2], al[mt][3], bh0, bh1);
                    mma_bf16(c1p, al[mt][0], al[mt][1], al[mt][2], al[mt][3], bh2, bh3);
                }
            }
        }
        __syncthreads();
    }

    // Epilogue
    int rq = lane >> 2;         // 0..7
    int cq = (lane & 3) * 2;    // 0,2,4,6
#pragma unroll
    for (int mt = 0; mt < 4; mt++) {
#pragma unroll
        for (int nt = 0; nt < 4; nt++) {
            int gc = bn + wn * 32 + nt * 8 + cq;
            float b0 = bias[gc], b1 = bias[gc + 1];
#pragma unroll
            for (int half = 0; half < 2; half++) {
                int grow = bm + wm * 64 + mt * 16 + rq + half * 8;
                float2 o;
                o.x = acc[mt][nt][half * 2 + 0] + b0;
                o.y = acc[mt][nt][half * 2 + 1] + b1;
                float* op;
                if (mode == 0) {
                    op = out + (size_t)grow * C_ + gc;
                } else {
                    int h = gc >> 6, d0 = gc & 63;
                    int b = grow >> 11, t = grow & (T_ - 1);
                    op = out + (((size_t)b * H_ + h) * T_ + t) * D_ + d0;
                }
                *(float2*)op = o;
            }
        }
    }
}

__global__ __launch_bounds__(256, 1) void mma_qkv_kernel(
        const float* __restrict__ bq, const float* __restrict__ bk,
        const float* __restrict__ bv) {
    int z = blockIdx.z;
    const __nv_bfloat16* Wh = g_wh + (size_t)z * C_ * C_;
    const __nv_bfloat16* Wl = g_wl + (size_t)z * C_ * C_;
    const float* bias = z == 0 ? bq : z == 1 ? bk : bv;
    float* dst = z == 0 ? g_q : z == 1 ? g_k : g_v;
    hmma_gemm_body(g_xh, g_xl, Wh, Wl, bias, dst, 1);
}

__global__ __launch_bounds__(256, 1) void mma_proj_kernel(
        const float* __restrict__ bp, float* __restrict__ out) {
    hmma_gemm_body(g_yh, g_yl, g_wh + 3 * (size_t)C_ * C_,
                   g_wl + 3 * (size_t)C_ * C_, bp, out, 0);
}

// ---------------------------------------------------------------------------
// Rotary
// ---------------------------------------------------------------------------
__global__ void rope_kernel() {
    const int NH = B_ * H_ * T_ * 32;
    int idx = blockIdx.x * blockDim.x + threadIdx.x;
    float* arr = g_q;
    if (idx >= NH) { arr = g_k; idx -= NH; }
    if (idx >= NH) return;
    int d = idx & 31;
    int row = idx >> 5;
    int t = row & (T_ - 1);
    float c = g_cos[(t << 6) + d];
    float s = g_sin[(t << 6) + d];
    size_t p = ((size_t)row << 6) + d;
    float x1 = arr[p], x2 = arr[p + 32];
    arr[p]      = x1 * c - x2 * s;
    arr[p + 32] = x2 * c + x1 * s;
}

// ---------------------------------------------------------------------------
// Flash-style causal attention (R1 version: 64 q / CTA, 1 q / thread)
// ---------------------------------------------------------------------------
__global__ __launch_bounds__(64) void attn_kernel() {
    __shared__ float Ks[64 * 64];
    __shared__ float Vs[64 * 64];
    __shared__ float Bsb[T_];

    int bh = blockIdx.y;
    int h = bh & (H_ - 1);
    int qb = gridDim.x - 1 - blockIdx.x;
    int q0 = qb << 6;
    int tid = threadIdx.x;

    const float* qptr  = g_q + ((size_t)bh * T_ + q0) * D_;
    const float* kbase = g_k + (size_t)bh * T_ * D_;
    const float* vbase = g_v + (size_t)bh * T_ * D_;

    {
        const float4* b4 = (const float4*)(g_bias + h * T_);
        for (int i = tid; i < T_ / 4; i += 64) ((float4*)Bsb)[i] = b4[i];
        const float4* q4 = (const float4*)qptr;
        for (int i = tid; i < 64 * 64 / 4; i += 64) ((float4*)Ks)[i] = q4[i];
    }
    __syncthreads();

    float qreg[64];
#pragma unroll
    for (int d = 0; d < 64; d++) qreg[d] = Ks[tid * 64 + d];

    int qi = q0 + tid;
    float mval = -CUDART_INF_F;
    float lval = 0.f;
    float acc[64];
#pragma unroll
    for (int d = 0; d < 64; d++) acc[d] = 0.f;

    for (int j0 = 0; j0 <= q0; j0 += 64) {
        __syncthreads();
        const float4* k4 = (const float4*)(kbase + (size_t)j0 * D_);
        const float4* v4 = (const float4*)(vbase + (size_t)j0 * D_);
        for (int i = tid; i < 1024; i += 64) {
            ((float4*)Ks)[i] = k4[i];
            ((float4*)Vs)[i] = v4[i];
        }
        __syncthreads();

        int jmax = qi - j0 + 1;
        if (jmax > 64) jmax = 64;
        for (int j = 0; j < jmax; j++) {
            const float* kr = Ks + j * 64;
            float s = 0.f;
#pragma unroll
            for (int d = 0; d < 64; d++) s += qreg[d] * kr[d];
            s = (s + Bsb[qi - j0 - j]) * 0.125f;

            const float* vr = Vs + j * 64;
            if (s > mval) {
                float corr = __expf(mval - s);
                mval = s;
                lval = lval * corr + 1.f;
#pragma unroll
                for (int d = 0; d < 64; d++) acc[d] = acc[d] * corr + vr[d];
            } else {
                float p = __expf(s - mval);
                lval += p;
#pragma unroll
                for (int d = 0; d < 64; d++) acc[d] += p * vr[d];
            }
        }
    }

    float inv = 1.f / lval;
    int b = bh >> 4;
    float* yo = g_y + ((size_t)b * T_ + qi) * C_ + h * D_;
#pragma unroll
    for (int d4 = 0; d4 < 16; d4++) {
        float4 o;
        o.x = acc[d4 * 4 + 0] * inv;
        o.y = acc[d4 * 4 + 1] * inv;
        o.z = acc[d4 * 4 + 2] * inv;
        o.w = acc[d4 * 4 + 3] * inv;
        ((float4*)yo)[d4] = o;
    }
}

// ---------------------------------------------------------------------------
extern "C" void kernel_launch(void* const* d_in, const int* in_sizes, int n_in,
                              void* d_out, int out_size) {
    const float* x   = (const float*)d_in[0];
    const float* Wq  = (const float*)d_in[1];
    const float* bq  = (const float*)d_in[2];
    const float* Wk  = (const float*)d_in[3];
    const float* bk  = (const float*)d_in[4];
    const float* Wv  = (const float*)d_in[5];
    const float* bv  = (const float*)d_in[6];
    const float* Wp  = (const float*)d_in[7];
    const float* bp  = (const float*)d_in[8];
    const float* tbl = (const float*)d_in[9];
    float* out = (float*)d_out;

    cudaFuncSetAttribute(mma_qkv_kernel,
                         cudaFuncAttributeMaxDynamicSharedMemorySize, SMEM_TOTAL);
    cudaFuncSetAttribute(mma_proj_kernel,
                         cudaFuncAttributeMaxDynamicSharedMemorySize, SMEM_TOTAL);

    tables_kernel<<<(T_ * D_ + 255) / 256, 256>>>(tbl);
    split_act_kernel<<<(B_ * T_ * C_ / 4) / 256, 256>>>(x, 0);
    split_w_kernel<<<dim3((C_ * C_ / 4) / 256, 4), 256>>>(Wq, Wk, Wv, Wp);

    mma_qkv_kernel<<<dim3(C_ / 128, (B_ * T_) / 128, 3), 256, SMEM_TOTAL>>>(bq, bk, bv);

    int rope_threads = 2 * B_ * H_ * T_ * 32;
    rope_kernel<<<(rope_threads + 255) / 256, 256>>>();

    attn_kernel<<<dim3(T_ / 64, B_ * H_), 64>>>();

    split_act_kernel<<<(B_ * T_ * C_ / 4) / 256, 256>>>(nullptr, 1);
    mma_proj_kernel<<<dim3(C_ / 128, (B_ * T_) / 128), 256, SMEM_TOTAL>>>(bp, out);
}

// round 5
// speedup vs baseline: 3.4204x; 2.3079x over previous
#include <cuda_runtime.h>
#include <cuda_bf16.h>
#include <math.h>
#include <math_constants.h>

#define B_  2
#define T_  2048
#define C_  1024
#define H_  16
#define D_  64
#define KCH 32               // GEMM K elems per pipeline chunk
#define NCH (C_ / KCH)       // 32 chunks

typedef unsigned int u32;

// ---------------------------------------------------------------------------
// Scratch (__device__ globals: allocation-free rule)
// ---------------------------------------------------------------------------
static __device__ __align__(16) float g_q[(size_t)B_*H_*T_*D_];
static __device__ __align__(16) float g_k[(size_t)B_*H_*T_*D_];
static __device__ __align__(16) float g_v[(size_t)B_*H_*T_*D_];
static __device__ __align__(16) float g_y[(size_t)B_*T_*C_];
static __device__ __align__(16) float g_bias[H_*T_];
static __device__ __align__(16) float g_cos[T_*D_];
static __device__ __align__(16) float g_sin[T_*D_];
// bf16 hi/lo operands for GEMMs
static __device__ __align__(16) __nv_bfloat16 g_xh[(size_t)B_*T_*C_];
static __device__ __align__(16) __nv_bfloat16 g_xl[(size_t)B_*T_*C_];
static __device__ __align__(16) __nv_bfloat16 g_yh[(size_t)B_*T_*C_];
static __device__ __align__(16) __nv_bfloat16 g_yl[(size_t)B_*T_*C_];
static __device__ __align__(16) __nv_bfloat16 g_wh[4 * (size_t)C_*C_];
static __device__ __align__(16) __nv_bfloat16 g_wl[4 * (size_t)C_*C_];
// bf16 hi/lo operands for attention (head layout [B,H,T,D])
static __device__ __align__(16) __nv_bfloat16 g_qbh[(size_t)B_*H_*T_*D_];
static __device__ __align__(16) __nv_bfloat16 g_qbl[(size_t)B_*H_*T_*D_];
static __device__ __align__(16) __nv_bfloat16 g_kbh[(size_t)B_*H_*T_*D_];
static __device__ __align__(16) __nv_bfloat16 g_kbl[(size_t)B_*H_*T_*D_];
static __device__ __align__(16) __nv_bfloat16 g_vbh[(size_t)B_*H_*T_*D_];
static __device__ __align__(16) __nv_bfloat16 g_vbl[(size_t)B_*H_*T_*D_];

// ---------------------------------------------------------------------------
// Baseline-PTX helpers (sm_80-compatible: ldmatrix / mma.sync / cp.async)
// ---------------------------------------------------------------------------
__device__ __forceinline__ u32 smem_u32(const void* p) {
    u32 a;
    asm("{ .reg .u64 t; cvta.to.shared.u64 t, %1; cvt.u32.u64 %0, t; }" : "=r"(a) : "l"(p));
    return a;
}
__device__ __forceinline__ void ldsm_x4(u32 addr, u32& r0, u32& r1, u32& r2, u32& r3) {
    asm volatile("ldmatrix.sync.aligned.m8n8.x4.shared.b16 {%0,%1,%2,%3}, [%4];"
                 : "=r"(r0), "=r"(r1), "=r"(r2), "=r"(r3) : "r"(addr));
}
__device__ __forceinline__ void ldsm_x4_t(u32 addr, u32& r0, u32& r1, u32& r2, u32& r3) {
    asm volatile("ldmatrix.sync.aligned.m8n8.x4.trans.shared.b16 {%0,%1,%2,%3}, [%4];"
                 : "=r"(r0), "=r"(r1), "=r"(r2), "=r"(r3) : "r"(addr));
}
__device__ __forceinline__ void mma_bf16(float* c, u32 a0, u32 a1, u32 a2, u32 a3,
                                         u32 b0, u32 b1) {
    asm volatile("mma.sync.aligned.m16n8k16.row.col.f32.bf16.bf16.f32 "
                 "{%0,%1,%2,%3}, {%4,%5,%6,%7}, {%8,%9}, {%0,%1,%2,%3};"
                 : "+f"(c[0]), "+f"(c[1]), "+f"(c[2]), "+f"(c[3])
                 : "r"(a0), "r"(a1), "r"(a2), "r"(a3), "r"(b0), "r"(b1));
}
#define CP_ASYNC16(dst, src) \
    asm volatile("cp.async.cg.shared.global [%0], [%1], 16;" :: "r"(dst), "l"(src))
#define CP_COMMIT() asm volatile("cp.async.commit_group;" ::: "memory")
#define CP_WAIT1()  asm volatile("cp.async.wait_group 1;" ::: "memory")
#define CP_WAIT0()  asm volatile("cp.async.wait_group 0;" ::: "memory")

__device__ __forceinline__ u32 pack_bf16(float lo, float hi) {
    u32 r;
    asm("cvt.rn.bf16x2.f32 %0, %1, %2;" : "=r"(r) : "f"(hi), "f"(lo));
    return r;
}

// ---------------------------------------------------------------------------
// Tables
// ---------------------------------------------------------------------------
__global__ void tables_kernel(const float* __restrict__ rel_table) {
    int idx = blockIdx.x * blockDim.x + threadIdx.x;
    if (idx < T_ * D_) {
        int t = idx >> 6;
        int d = idx & 63;
        int j = d & 31;
        float inv = (float)pow(10000.0, -(double)(2 * j) / 64.0);
        float fr = (float)t * inv;
        g_cos[idx] = cosf(fr);
        g_sin[idx] = sinf(fr);
    }
    if (idx < H_ * T_) {
        int h = idx / T_;
        int n = idx % T_;
        int bucket;
        if (n < 16) {
            bucket = n;
        } else {
            float v = logf((float)n * (1.0f / 16.0f)) / 2.0794415416798357f * 16.0f;
            bucket = 16 + (int)v;
            if (bucket > 31) bucket = 31;
        }
        g_bias[idx] = rel_table[bucket * H_ + h];
    }
}

// ---------------------------------------------------------------------------
// fp32 -> bf16 hi/lo splits
// ---------------------------------------------------------------------------
__device__ __forceinline__ void split1(float v, __nv_bfloat16& h, __nv_bfloat16& l) {
    h = __float2bfloat16(v);
    l = __float2bfloat16(v - __bfloat162float(h));
}

__global__ void split_act_kernel(const float* __restrict__ xin, int which) {
    const float* src = which == 0 ? xin : g_y;
    __nv_bfloat16* oh = which == 0 ? g_xh : g_yh;
    __nv_bfloat16* ol = which == 0 ? g_xl : g_yl;
    int i = blockIdx.x * 256 + threadIdx.x;
    float4 v = ((const float4*)src)[i];
    __nv_bfloat16 h0, h1, h2, h3, l0, l1, l2, l3;
    split1(v.x, h0, l0); split1(v.y, h1, l1);
    split1(v.z, h2, l2); split1(v.w, h3, l3);
    ((__nv_bfloat162*)oh)[i * 2 + 0] = __nv_bfloat162(h0, h1);
    ((__nv_bfloat162*)oh)[i * 2 + 1] = __nv_bfloat162(h2, h3);
    ((__nv_bfloat162*)ol)[i * 2 + 0] = __nv_bfloat162(l0, l1);
    ((__nv_bfloat162*)ol)[i * 2 + 1] = __nv_bfloat162(l2, l3);
}

__global__ void split_w_kernel(const float* __restrict__ Wq, const float* __restrict__ Wk,
                               const float* __restrict__ Wv, const float* __restrict__ Wp) {
    int z = blockIdx.y;
    const float* W = z == 0 ? Wq : z == 1 ? Wk : z == 2 ? Wv : Wp;
    __nv_bfloat16* oh = g_wh + (size_t)z * C_ * C_;
    __nv_bfloat16* ol = g_wl + (size_t)z * C_ * C_;
    int i = blockIdx.x * 256 + threadIdx.x;
    float4 v = ((const float4*)W)[i];
    __nv_bfloat16 h0, h1, h2, h3, l0, l1, l2, l3;
    split1(v.x, h0, l0); split1(v.y, h1, l1);
    split1(v.z, h2, l2); split1(v.w, h3, l3);
    ((__nv_bfloat162*)oh)[i * 2 + 0] = __nv_bfloat162(h0, h1);
    ((__nv_bfloat162*)oh)[i * 2 + 1] = __nv_bfloat162(h2, h3);
    ((__nv_bfloat162*)ol)[i * 2 + 0] = __nv_bfloat162(l0, l1);
    ((__nv_bfloat162*)ol)[i * 2 + 1] = __nv_bfloat162(l2, l3);
}

// ---------------------------------------------------------------------------
// HMMA GEMM (unchanged from R4): 128x128 CTA, 8 warps, cp.async 2-stage
// ---------------------------------------------------------------------------
#define SA 40
#define SB 136
#define AH_OFF 0
#define AL_OFF (128 * SA * 2)
#define BH_OFF (AL_OFF + 128 * SA * 2)
#define BL_OFF (BH_OFF + KCH * SB * 2)
#define STAGE_BYTES (BL_OFF + KCH * SB * 2)
#define SMEM_TOTAL (2 * STAGE_BYTES)

__device__ __forceinline__ void hmma_gemm_body(
        const __nv_bfloat16* __restrict__ Ah, const __nv_bfloat16* __restrict__ Al,
        const __nv_bfloat16* __restrict__ Wh, const __nv_bfloat16* __restrict__ Wl,
        const float* __restrict__ bias, float* __restrict__ out, int mode) {
    extern __shared__ char smem[];
    u32 sb = smem_u32(smem);

    int tid = threadIdx.x;
    int lane = tid & 31;
    int wid = tid >> 5;
    int wm = wid & 1;
    int wn = wid >> 1;
    int bm = blockIdx.y * 128;
    int bn = blockIdx.x * 128;

    float acc[4][4][4];
#pragma unroll
    for (int i = 0; i < 4; i++)
#pragma unroll
        for (int j = 0; j < 4; j++)
#pragma unroll
            for (int r = 0; r < 4; r++) acc[i][j][r] = 0.f;

    auto load_chunk = [&](int c, int s) {
        u32 st = sb + s * STAGE_BYTES;
        int c0 = c * KCH;
#pragma unroll
        for (int u = tid; u < 512; u += 256) {
            int row = u >> 2, seg = u & 3;
            size_t gofs = (size_t)(bm + row) * C_ + c0 + seg * 8;
            u32 dofs = (u32)(row * SA + seg * 8) * 2;
            CP_ASYNC16(st + AH_OFF + dofs, Ah + gofs);
            CP_ASYNC16(st + AL_OFF + dofs, Al + gofs);
        }
#pragma unroll
        for (int u = tid; u < 512; u += 256) {
            int row = u >> 4, seg = u & 15;
            size_t gofs = (size_t)(c0 + row) * C_ + bn + seg * 8;
            u32 dofs = (u32)(row * SB + seg * 8) * 2;
            CP_ASYNC16(st + BH_OFF + dofs, Wh + gofs);
            CP_ASYNC16(st + BL_OFF + dofs, Wl + gofs);
        }
        CP_COMMIT();
    };

    load_chunk(0, 0);

    for (int c = 0; c < NCH; c++) {
        int s = c & 1;
        if (c + 1 < NCH) { load_chunk(c + 1, s ^ 1); CP_WAIT1(); }
        else             { CP_WAIT0(); }
        __syncthreads();

        u32 st = sb + s * STAGE_BYTES;
        int lr = lane & 15;
        int lh = lane >> 4;
#pragma unroll
        for (int ks = 0; ks < 2; ks++) {
            int k0 = ks * 16;
            u32 ah[4][4], al[4][4];
#pragma unroll
            for (int mt = 0; mt < 4; mt++) {
                u32 arow = (u32)(wm * 64 + mt * 16 + lr);
                u32 aoff = (arow * SA + k0 + lh * 8) * 2;
                ldsm_x4(st + AH_OFF + aoff, ah[mt][0], ah[mt][1], ah[mt][2], ah[mt][3]);
                ldsm_x4(st + AL_OFF + aoff, al[mt][0], al[mt][1], al[mt][2], al[mt][3]);
            }
#pragma unroll
            for (int np = 0; np < 2; np++) {
                u32 brow = (u32)(k0 + lr);
                u32 bcol = (u32)(wn * 32 + np * 16 + lh * 8);
                u32 boff = (brow * SB + bcol) * 2;
                u32 bh0, bh1, bh2, bh3, bl0, bl1, bl2, bl3;
                ldsm_x4_t(st + BH_OFF + boff, bh0, bh1, bh2, bh3);
                ldsm_x4_t(st + BL_OFF + boff, bl0, bl1, bl2, bl3);
#pragma unroll
                for (int mt = 0; mt < 4; mt++) {
                    float* c0p = acc[mt][np * 2];
                    float* c1p = acc[mt][np * 2 + 1];
                    mma_bf16(c0p, ah[mt][0], ah[mt][1], ah[mt][2], ah[mt][3], bh0, bh1);
                    mma_bf16(c1p, ah[mt][0], ah[mt][1], ah[mt][2], ah[mt][3], bh2, bh3);
                    mma_bf16(c0p, ah[mt][0], ah[mt][1], ah[mt][2], ah[mt][3], bl0, bl1);
                    mma_bf16(c1p, ah[mt][0], ah[mt][1], ah[mt][2], ah[mt][3], bl2, bl3);
                    mma_bf16(c0p, al[mt][0], al[mt][1], al[mt][2], al[mt][3], bh0, bh1);
                    mma_bf16(c1p, al[mt][0], al[mt][1], al[mt][2], al[mt][3], bh2, bh3);
                }
            }
        }
        __syncthreads();
    }

    int rq = lane >> 2;
    int cq = (lane & 3) * 2;
#pragma unroll
    for (int mt = 0; mt < 4; mt++) {
#pragma unroll
        for (int nt = 0; nt < 4; nt++) {
            int gc = bn + wn * 32 + nt * 8 + cq;
            float b0 = bias[gc], b1 = bias[gc + 1];
#pragma unroll
            for (int half = 0; half < 2; half++) {
                int grow = bm + wm * 64 + mt * 16 + rq + half * 8;
                float2 o;
                o.x = acc[mt][nt][half * 2 + 0] + b0;
                o.y = acc[mt][nt][half * 2 + 1] + b1;
                float* op;
                if (mode == 0) {
                    op = out + (size_t)grow * C_ + gc;
                } else {
                    int h = gc >> 6, d0 = gc & 63;
                    int b = grow >> 11, t = grow & (T_ - 1);
                    op = out + (((size_t)b * H_ + h) * T_ + t) * D_ + d0;
                }
                *(float2*)op = o;
            }
        }
    }
}

__global__ __launch_bounds__(256, 1) void mma_qkv_kernel(
        const float* __restrict__ bq, const float* __restrict__ bk,
        const float* __restrict__ bv) {
    int z = blockIdx.z;
    const __nv_bfloat16* Wh = g_wh + (size_t)z * C_ * C_;
    const __nv_bfloat16* Wl = g_wl + (size_t)z * C_ * C_;
    const float* bias = z == 0 ? bq : z == 1 ? bk : bv;
    float* dst = z == 0 ? g_q : z == 1 ? g_k : g_v;
    hmma_gemm_body(g_xh, g_xl, Wh, Wl, bias, dst, 1);
}

__global__ __launch_bounds__(256, 1) void mma_proj_kernel(
        const float* __restrict__ bp, float* __restrict__ out) {
    hmma_gemm_body(g_yh, g_yl, g_wh + 3 * (size_t)C_ * C_,
                   g_wl + 3 * (size_t)C_ * C_, bp, out, 0);
}

// ---------------------------------------------------------------------------
// Rope + bf16 hi/lo split. seg 0: q (rotate + 1/8 scale), 1: k (rotate), 2: v
// ---------------------------------------------------------------------------
__global__ void rope_split_kernel() {
    const int NH = B_ * H_ * T_ * 32;
    int idx = blockIdx.x * 256 + threadIdx.x;
    int seg = idx / NH;
    int r = idx - seg * NH;
    int d = r & 31;
    int row = r >> 5;
    int t = row & (T_ - 1);
    size_t p = ((size_t)row << 6) + d;

    float y1, y2;
    __nv_bfloat16 *oh, *ol;
    if (seg == 0) {
        float c = g_cos[(t << 6) + d], s = g_sin[(t << 6) + d];
        float x1 = g_q[p], x2 = g_q[p + 32];
        y1 = (x1 * c - x2 * s) * 0.125f;
        y2 = (x2 * c + x1 * s) * 0.125f;
        oh = g_qbh; ol = g_qbl;
    } else if (seg == 1) {
        float c = g_cos[(t << 6) + d], s = g_sin[(t << 6) + d];
        float x1 = g_k[p], x2 = g_k[p + 32];
        y1 = x1 * c - x2 * s;
        y2 = x2 * c + x1 * s;
        oh = g_kbh; ol = g_kbl;
    } else {
        y1 = g_v[p]; y2 = g_v[p + 32];
        oh = g_vbh; ol = g_vbl;
    }
    __nv_bfloat16 h1, l1, h2, l2;
    split1(y1, h1, l1); split1(y2, h2, l2);
    oh[p] = h1; oh[p + 32] = h2;
    ol[p] = l1; ol[p + 32] = l2;
}

// ---------------------------------------------------------------------------
// HMMA flash attention. CTA: 128 queries x one (b,h). 8 warps x 16 rows.
// Key blocks of 64, double-buffered cp.async. Q/K and P/V hi/lo bf16 splits.
// ---------------------------------------------------------------------------
#define AST 72                               // smem row stride in halves
#define KV_ARRB (64 * AST * 2)               // 9216 B per array
#define KV_STAGEB (4 * KV_ARRB)              // 36864 B per stage
#define AT_SMEM (2 * KV_STAGEB + T_ * 4)     // + bias row = 81920 B

__global__ __launch_bounds__(256, 1) void attn_mma_kernel() {
    extern __shared__ char asm_[];
    u32 sbase = smem_u32(asm_);
    float* sbias = (float*)(asm_ + 2 * KV_STAGEB);
    __nv_bfloat16* sst = (__nv_bfloat16*)asm_;

    int bh = blockIdx.y;
    int h = bh & (H_ - 1);
    int qb = gridDim.x - 1 - blockIdx.x;      // big-work CTAs first
    int q0 = qb * 128;
    int tid = threadIdx.x;
    int lane = tid & 31;
    int w = tid >> 5;
    int qw = q0 + w * 16;                     // warp's first query row

    const __nv_bfloat16* qbh = g_qbh + ((size_t)bh * T_ + q0) * D_;
    const __nv_bfloat16* qbl = g_qbl + ((size_t)bh * T_ + q0) * D_;
    size_t kvo = (size_t)bh * T_ * D_;

    // bias row (pre-scaled by 1/8)
    {
        const float4* b4 = (const float4*)(g_bias + h * T_);
        for (int i = tid; i < T_ / 4; i += 256) {
            float4 v = b4[i];
            v.x *= 0.125f; v.y *= 0.125f; v.z *= 0.125f; v.w *= 0.125f;
            ((float4*)sbias)[i] = v;
        }
    }
    // stage Q hi/lo into stage0 area
    for (int u = tid; u < 1024; u += 256) {
        int row = u >> 3, seg = u & 7;
        *(uint4*)(sst + row * AST + seg * 8) =
            *(const uint4*)(qbh + row * 64 + seg * 8);
        *(uint4*)(sst + 128 * AST + row * AST + seg * 8) =
            *(const uint4*)(qbl + row * 64 + seg * 8);
    }
    __syncthreads();

    // Q fragments
    u32 qfh[4][4], qfl[4][4];
    {
        int lr = lane & 15, lh = lane >> 4;
#pragma unroll
        for (int kc = 0; kc < 4; kc++) {
            u32 off = (u32)((w * 16 + lr) * AST + kc * 16 + lh * 8) * 2;
            ldsm_x4(sbase + off, qfh[kc][0], qfh[kc][1], qfh[kc][2], qfh[kc][3]);
            ldsm_x4(sbase + 128 * AST * 2 + off, qfl[kc][0], qfl[kc][1], qfl[kc][2], qfl[kc][3]);
        }
    }
    __syncthreads();

    auto load_kv = [&](int blk, int s) {
        u32 st = sbase + s * KV_STAGEB;
        const __nv_bfloat16* kh = g_kbh + kvo + (size_t)blk * 64 * 64;
        const __nv_bfloat16* kl = g_kbl + kvo + (size_t)blk * 64 * 64;
        const __nv_bfloat16* vh = g_vbh + kvo + (size_t)blk * 64 * 64;
        const __nv_bfloat16* vl = g_vbl + kvo + (size_t)blk * 64 * 64;
#pragma unroll
        for (int u = tid; u < 512; u += 256) {
            int row = u >> 3, seg = u & 7;
            u32 doff = (u32)(row * AST + seg * 8) * 2;
            int goff = row * 64 + seg * 8;
            CP_ASYNC16(st + doff,              kh + goff);
            CP_ASYNC16(st + KV_ARRB + doff,    kl + goff);
            CP_ASYNC16(st + 2*KV_ARRB + doff,  vh + goff);
            CP_ASYNC16(st + 3*KV_ARRB + doff,  vl + goff);
        }
        CP_COMMIT();
    };

    int nblk = q0 / 64 + 2;
    load_kv(0, 0);

    float mlo = -CUDART_INF_F, mhi = -CUDART_INF_F;
    float llo = 0.f, lhi = 0.f;
    float oacc[8][4];
#pragma unroll
    for (int i = 0; i < 8; i++)
#pragma unroll
        for (int j = 0; j < 4; j++) oacc[i][j] = 0.f;

    int rlo = qw + (lane >> 2);
    int rhi = rlo + 8;
    int cq = (lane & 3) * 2;

    for (int blk = 0; blk < nblk; blk++) {
        int s = blk & 1;
        if (blk + 1 < nblk) { load_kv(blk + 1, s ^ 1); CP_WAIT1(); }
        else                { CP_WAIT0(); }
        __syncthreads();

        int j0 = blk * 64;
        if (j0 <= qw + 15) {
            u32 st = sbase + s * KV_STAGEB;
            int lr = lane & 15, lh = lane >> 4;

            // S = Qh Kh^T + Qh Kl^T + Ql Kh^T
            float sacc[8][4];
#pragma unroll
            for (int i = 0; i < 8; i++)
#pragma unroll
                for (int j = 0; j < 4; j++) sacc[i][j] = 0.f;
#pragma unroll
            for (int kg = 0; kg < 4; kg++) {
#pragma unroll
                for (int kc = 0; kc < 4; kc++) {
                    u32 off = (u32)((kg * 16 + lr) * AST + kc * 16 + lh * 8) * 2;
                    u32 kh0, kh1, kh2, kh3, kl0, kl1, kl2, kl3;
                    ldsm_x4(st + off, kh0, kh1, kh2, kh3);
                    ldsm_x4(st + KV_ARRB + off, kl0, kl1, kl2, kl3);
                    float* e = sacc[2 * kg];
                    float* o = sacc[2 * kg + 1];
                    mma_bf16(e, qfh[kc][0], qfh[kc][1], qfh[kc][2], qfh[kc][3], kh0, kh2);
                    mma_bf16(o, qfh[kc][0], qfh[kc][1], qfh[kc][2], qfh[kc][3], kh1, kh3);
                    mma_bf16(e, qfh[kc][0], qfh[kc][1], qfh[kc][2], qfh[kc][3], kl0, kl2);
                    mma_bf16(o, qfh[kc][0], qfh[kc][1], qfh[kc][2], qfh[kc][3], kl1, kl3);
                    mma_bf16(e, qfl[kc][0], qfl[kc][1], qfl[kc][2], qfl[kc][3], kh0, kh2);
                    mma_bf16(o, qfl[kc][0], qfl[kc][1], qfl[kc][2], qfl[kc][3], kh1, kh3);
                }
            }

            // bias + causal mask
#pragma unroll
            for (int nf = 0; nf < 8; nf++) {
                int jc = j0 + nf * 8 + cq;
                int d0 = rlo - jc;
                int d2 = rhi - jc;
                sacc[nf][0] = (d0 >= 0) ? sacc[nf][0] + sbias[d0]     : -CUDART_INF_F;
                sacc[nf][1] = (d0 >= 1) ? sacc[nf][1] + sbias[d0 - 1] : -CUDART_INF_F;
                sacc[nf][2] = (d2 >= 0) ? sacc[nf][2] + sbias[d2]     : -CUDART_INF_F;
                sacc[nf][3] = (d2 >= 1) ? sacc[nf][3] + sbias[d2 - 1] : -CUDART_INF_F;
            }

            // row max
            float bmlo = sacc[0][0], bmhi = sacc[0][2];
#pragma unroll
            for (int nf = 0; nf < 8; nf++) {
                bmlo = fmaxf(bmlo, fmaxf(sacc[nf][0], sacc[nf][1]));
                bmhi = fmaxf(bmhi, fmaxf(sacc[nf][2], sacc[nf][3]));
            }
            bmlo = fmaxf(bmlo, __shfl_xor_sync(0xffffffffu, bmlo, 1));
            bmlo = fmaxf(bmlo, __shfl_xor_sync(0xffffffffu, bmlo, 2));
            bmhi = fmaxf(bmhi, __shfl_xor_sync(0xffffffffu, bmhi, 1));
            bmhi = fmaxf(bmhi, __shfl_xor_sync(0xffffffffu, bmhi, 2));

            float nmlo = fmaxf(mlo, bmlo), nmhi = fmaxf(mhi, bmhi);
            float clo = __expf(mlo - nmlo), chi = __expf(mhi - nmhi);
            mlo = nmlo; mhi = nmhi;
            llo *= clo; lhi *= chi;
#pragma unroll
            for (int nf = 0; nf < 8; nf++) {
                oacc[nf][0] *= clo; oacc[nf][1] *= clo;
                oacc[nf][2] *= chi; oacc[nf][3] *= chi;
            }

            // exp -> P, pack hi/lo fragments
            u32 pfh[4][4], pfl[4][4];
#pragma unroll
            for (int nf = 0; nf < 8; nf++) {
                float p0 = __expf(sacc[nf][0] - mlo);
                float p1 = __expf(sacc[nf][1] - mlo);
                float p2 = __expf(sacc[nf][2] - mhi);
                float p3 = __expf(sacc[nf][3] - mhi);
                llo += p0 + p1;
                lhi += p2 + p3;
                __nv_bfloat16 h0, l0, h1, l1, h2, l2, h3, l3;
                split1(p0, h0, l0); split1(p1, h1, l1);
                split1(p2, h2, l2); split1(p3, h3, l3);
                int kc = nf >> 1, half = nf & 1;
                pfh[kc][half * 2 + 0] = (u32)__nv_bfloat162(h0, h1).y << 16 | ((u32)__nv_bfloat162(h0, h1).x & 0xffffu);
                // (constructed below properly)
                pfh[kc][half * 2 + 0] = pack_bf16(__bfloat162float(h0), __bfloat162float(h1));
                pfh[kc][half * 2 + 1] = pack_bf16(__bfloat162float(h2), __bfloat162float(h3));
                pfl[kc][half * 2 + 0] = pack_bf16(__bfloat162float(l0), __bfloat162float(l1));
                pfl[kc][half * 2 + 1] = pack_bf16(__bfloat162float(l2), __bfloat162float(l3));
            }

            // O += P V : Ph Vh + Ph Vl + Pl Vh
#pragma unroll
            for (int dg = 0; dg < 4; dg++) {
#pragma unroll
                for (int kc = 0; kc < 4; kc++) {
                    u32 off = (u32)((kc * 16 + lr) * AST + dg * 16 + lh * 8) * 2;
                    u32 vh0, vh1, vh2, vh3, vl0, vl1, vl2, vl3;
                    ldsm_x4_t(st + 2*KV_ARRB + off, vh0, vh1, vh2, vh3);
                    ldsm_x4_t(st + 3*KV_ARRB + off, vl0, vl1, vl2, vl3);
                    float* e = oacc[2 * dg];
                    float* o = oacc[2 * dg + 1];
                    mma_bf16(e, pfh[kc][0], pfh[kc][1], pfh[kc][2], pfh[kc][3], vh0, vh1);
                    mma_bf16(o, pfh[kc][0], pfh[kc][1], pfh[kc][2], pfh[kc][3], vh2, vh3);
                    mma_bf16(e, pfh[kc][0], pfh[kc][1], pfh[kc][2], pfh[kc][3], vl0, vl1);
                    mma_bf16(o, pfh[kc][0], pfh[kc][1], pfh[kc][2], pfh[kc][3], vl2, vl3);
                    mma_bf16(e, pfl[kc][0], pfl[kc][1], pfl[kc][2], pfl[kc][3], vh0, vh1);
                    mma_bf16(o, pfl[kc][0], pfl[kc][1], pfl[kc][2], pfl[kc][3], vh2, vh3);
                }
            }
        }
        __syncthreads();
    }

    // final l reduce + write
    llo += __shfl_xor_sync(0xffffffffu, llo, 1);
    llo += __shfl_xor_sync(0xffffffffu, llo, 2);
    lhi += __shfl_xor_sync(0xffffffffu, lhi, 1);
    lhi += __shfl_xor_sync(0xffffffffu, lhi, 2);
    float ilo = 1.f / llo, ihi = 1.f / lhi;

    int b = bh >> 4;
    float* ylo = g_y + ((size_t)b * T_ + rlo) * C_ + h * D_ + cq;
    float* yhi = g_y + ((size_t)b * T_ + rhi) * C_ + h * D_ + cq;
#pragma unroll
    for (int nf = 0; nf < 8; nf++) {
        *(float2*)(ylo + nf * 8) = make_float2(oacc[nf][0] * ilo, oacc[nf][1] * ilo);
        *(float2*)(yhi + nf * 8) = make_float2(oacc[nf][2] * ihi, oacc[nf][3] * ihi);
    }
}

// ---------------------------------------------------------------------------
extern "C" void kernel_launch(void* const* d_in, const int* in_sizes, int n_in,
                              void* d_out, int out_size) {
    const float* x   = (const float*)d_in[0];
    const float* Wq  = (const float*)d_in[1];
    const float* bq  = (const float*)d_in[2];
    const float* Wk  = (const float*)d_in[3];
    const float* bk  = (const float*)d_in[4];
    const float* Wv  = (const float*)d_in[5];
    const float* bv  = (const float*)d_in[6];
    const float* Wp  = (const float*)d_in[7];
    const float* bp  = (const float*)d_in[8];
    const float* tbl = (const float*)d_in[9];
    float* out = (float*)d_out;

    cudaFuncSetAttribute(mma_qkv_kernel,
                         cudaFuncAttributeMaxDynamicSharedMemorySize, SMEM_TOTAL);
    cudaFuncSetAttribute(mma_proj_kernel,
                         cudaFuncAttributeMaxDynamicSharedMemorySize, SMEM_TOTAL);
    cudaFuncSetAttribute(attn_mma_kernel,
                         cudaFuncAttributeMaxDynamicSharedMemorySize, AT_SMEM);

    tables_kernel<<<(T_ * D_ + 255) / 256, 256>>>(tbl);
    split_act_kernel<<<(B_ * T_ * C_ / 4) / 256, 256>>>(x, 0);
    split_w_kernel<<<dim3((C_ * C_ / 4) / 256, 4), 256>>>(Wq, Wk, Wv, Wp);

    mma_qkv_kernel<<<dim3(C_ / 128, (B_ * T_) / 128, 3), 256, SMEM_TOTAL>>>(bq, bk, bv);

    rope_split_kernel<<<(3 * B_ * H_ * T_ * 32) / 256, 256>>>();

    attn_mma_kernel<<<dim3(T_ / 128, B_ * H_), 256, AT_SMEM>>>();

    split_act_kernel<<<(B_ * T_ * C_ / 4) / 256, 256>>>(nullptr, 1);
    mma_proj_kernel<<<dim3(C_ / 128, (B_ * T_) / 128), 256, SMEM_TOTAL>>>(bp, out);
}

// round 6
// speedup vs baseline: 3.4484x; 1.0082x over previous
#include <cuda_runtime.h>
#include <cuda_bf16.h>
#include <math.h>
#include <math_constants.h>

#define B_  2
#define T_  2048
#define C_  1024
#define H_  16
#define D_  64
#define KCH 64               // GEMM K elems per pipeline chunk
#define NCH (C_ / KCH)       // 16 chunks

typedef unsigned int u32;

// ---------------------------------------------------------------------------
// Scratch (__device__ globals: allocation-free rule)
// ---------------------------------------------------------------------------
static __device__ __align__(16) float g_q[(size_t)B_*H_*T_*D_];
static __device__ __align__(16) float g_k[(size_t)B_*H_*T_*D_];
static __device__ __align__(16) float g_v[(size_t)B_*H_*T_*D_];
static __device__ __align__(16) float g_y[(size_t)B_*T_*C_];
static __device__ __align__(16) float g_bias[H_*T_];
static __device__ __align__(16) float g_cos[T_*D_];
static __device__ __align__(16) float g_sin[T_*D_];
// bf16 hi/lo operands for GEMMs
static __device__ __align__(16) __nv_bfloat16 g_xh[(size_t)B_*T_*C_];
static __device__ __align__(16) __nv_bfloat16 g_xl[(size_t)B_*T_*C_];
static __device__ __align__(16) __nv_bfloat16 g_yh[(size_t)B_*T_*C_];
static __device__ __align__(16) __nv_bfloat16 g_yl[(size_t)B_*T_*C_];
static __device__ __align__(16) __nv_bfloat16 g_wh[4 * (size_t)C_*C_];
static __device__ __align__(16) __nv_bfloat16 g_wl[4 * (size_t)C_*C_];
// bf16 hi/lo operands for attention (head layout [B,H,T,D])
static __device__ __align__(16) __nv_bfloat16 g_qbh[(size_t)B_*H_*T_*D_];
static __device__ __align__(16) __nv_bfloat16 g_qbl[(size_t)B_*H_*T_*D_];
static __device__ __align__(16) __nv_bfloat16 g_kbh[(size_t)B_*H_*T_*D_];
static __device__ __align__(16) __nv_bfloat16 g_kbl[(size_t)B_*H_*T_*D_];
static __device__ __align__(16) __nv_bfloat16 g_vbh[(size_t)B_*H_*T_*D_];
static __device__ __align__(16) __nv_bfloat16 g_vbl[(size_t)B_*H_*T_*D_];

// ---------------------------------------------------------------------------
// Baseline-PTX helpers (sm_80-compatible: ldmatrix / mma.sync / cp.async)
// ---------------------------------------------------------------------------
__device__ __forceinline__ u32 smem_u32(const void* p) {
    u32 a;
    asm("{ .reg .u64 t; cvta.to.shared.u64 t, %1; cvt.u32.u64 %0, t; }" : "=r"(a) : "l"(p));
    return a;
}
__device__ __forceinline__ void ldsm_x4(u32 addr, u32& r0, u32& r1, u32& r2, u32& r3) {
    asm volatile("ldmatrix.sync.aligned.m8n8.x4.shared.b16 {%0,%1,%2,%3}, [%4];"
                 : "=r"(r0), "=r"(r1), "=r"(r2), "=r"(r3) : "r"(addr));
}
__device__ __forceinline__ void ldsm_x4_t(u32 addr, u32& r0, u32& r1, u32& r2, u32& r3) {
    asm volatile("ldmatrix.sync.aligned.m8n8.x4.trans.shared.b16 {%0,%1,%2,%3}, [%4];"
                 : "=r"(r0), "=r"(r1), "=r"(r2), "=r"(r3) : "r"(addr));
}
__device__ __forceinline__ void mma_bf16(float* c, u32 a0, u32 a1, u32 a2, u32 a3,
                                         u32 b0, u32 b1) {
    asm volatile("mma.sync.aligned.m16n8k16.row.col.f32.bf16.bf16.f32 "
                 "{%0,%1,%2,%3}, {%4,%5,%6,%7}, {%8,%9}, {%0,%1,%2,%3};"
                 : "+f"(c[0]), "+f"(c[1]), "+f"(c[2]), "+f"(c[3])
                 : "r"(a0), "r"(a1), "r"(a2), "r"(a3), "r"(b0), "r"(b1));
}
#define CP_ASYNC16(dst, src) \
    asm volatile("cp.async.cg.shared.global [%0], [%1], 16;" :: "r"(dst), "l"(src))
#define CP_COMMIT() asm volatile("cp.async.commit_group;" ::: "memory")
#define CP_WAIT1()  asm volatile("cp.async.wait_group 1;" ::: "memory")
#define CP_WAIT0()  asm volatile("cp.async.wait_group 0;" ::: "memory")

__device__ __forceinline__ u32 pack_bf16(float lo, float hi) {
    u32 r;
    asm("cvt.rn.bf16x2.f32 %0, %1, %2;" : "=r"(r) : "f"(hi), "f"(lo));
    return r;
}

// ---------------------------------------------------------------------------
// Tables
// ---------------------------------------------------------------------------
__global__ void tables_kernel(const float* __restrict__ rel_table) {
    int idx = blockIdx.x * blockDim.x + threadIdx.x;
    if (idx < T_ * D_) {
        int t = idx >> 6;
        int d = idx & 63;
        int j = d & 31;
        float inv = (float)pow(10000.0, -(double)(2 * j) / 64.0);
        float fr = (float)t * inv;
        g_cos[idx] = cosf(fr);
        g_sin[idx] = sinf(fr);
    }
    if (idx < H_ * T_) {
        int h = idx / T_;
        int n = idx % T_;
        int bucket;
        if (n < 16) {
            bucket = n;
        } else {
            float v = logf((float)n * (1.0f / 16.0f)) / 2.0794415416798357f * 16.0f;
            bucket = 16 + (int)v;
            if (bucket > 31) bucket = 31;
        }
        g_bias[idx] = rel_table[bucket * H_ + h];
    }
}

// ---------------------------------------------------------------------------
// fp32 -> bf16 hi/lo splits
// ---------------------------------------------------------------------------
__device__ __forceinline__ void split1(float v, __nv_bfloat16& h, __nv_bfloat16& l) {
    h = __float2bfloat16(v);
    l = __float2bfloat16(v - __bfloat162float(h));
}

__global__ void split_act_kernel(const float* __restrict__ xin, int which) {
    const float* src = which == 0 ? xin : g_y;
    __nv_bfloat16* oh = which == 0 ? g_xh : g_yh;
    __nv_bfloat16* ol = which == 0 ? g_xl : g_yl;
    int i = blockIdx.x * 256 + threadIdx.x;
    float4 v = ((const float4*)src)[i];
    __nv_bfloat16 h0, h1, h2, h3, l0, l1, l2, l3;
    split1(v.x, h0, l0); split1(v.y, h1, l1);
    split1(v.z, h2, l2); split1(v.w, h3, l3);
    ((__nv_bfloat162*)oh)[i * 2 + 0] = __nv_bfloat162(h0, h1);
    ((__nv_bfloat162*)oh)[i * 2 + 1] = __nv_bfloat162(h2, h3);
    ((__nv_bfloat162*)ol)[i * 2 + 0] = __nv_bfloat162(l0, l1);
    ((__nv_bfloat162*)ol)[i * 2 + 1] = __nv_bfloat162(l2, l3);
}

__global__ void split_w_kernel(const float* __restrict__ Wq, const float* __restrict__ Wk,
                               const float* __restrict__ Wv, const float* __restrict__ Wp) {
    int z = blockIdx.y;
    const float* W = z == 0 ? Wq : z == 1 ? Wk : z == 2 ? Wv : Wp;
    __nv_bfloat16* oh = g_wh + (size_t)z * C_ * C_;
    __nv_bfloat16* ol = g_wl + (size_t)z * C_ * C_;
    int i = blockIdx.x * 256 + threadIdx.x;
    float4 v = ((const float4*)W)[i];
    __nv_bfloat16 h0, h1, h2, h3, l0, l1, l2, l3;
    split1(v.x, h0, l0); split1(v.y, h1, l1);
    split1(v.z, h2, l2); split1(v.w, h3, l3);
    ((__nv_bfloat162*)oh)[i * 2 + 0] = __nv_bfloat162(h0, h1);
    ((__nv_bfloat162*)oh)[i * 2 + 1] = __nv_bfloat162(h2, h3);
    ((__nv_bfloat162*)ol)[i * 2 + 0] = __nv_bfloat162(l0, l1);
    ((__nv_bfloat162*)ol)[i * 2 + 1] = __nv_bfloat162(l2, l3);
}

// ---------------------------------------------------------------------------
// HMMA GEMM v2: 128x128 CTA tile, 512 threads (16 warps, 4x4, warp tile 32x32),
// K chunks of 64, 2-stage cp.async pipeline.
// mode 0: row-major out; mode 1: head layout [B,H,T,D].
// ---------------------------------------------------------------------------
#define SA 72        // A smem row stride (halves): 64 + 8 pad
#define SB 136       // B smem row stride (halves): 128 + 8 pad
#define AH_OFF 0
#define AL_OFF (128 * SA * 2)                     // 18432
#define BH_OFF (2 * 128 * SA * 2)                 // 36864
#define BL_OFF (BH_OFF + KCH * SB * 2)            // 54272
#define STAGE_BYTES (BL_OFF + KCH * SB * 2 - 0)   // 71680
#define SMEM_TOTAL (2 * STAGE_BYTES)              // 143360

__device__ __forceinline__ void hmma_gemm_body(
        const __nv_bfloat16* __restrict__ Ah, const __nv_bfloat16* __restrict__ Al,
        const __nv_bfloat16* __restrict__ Wh, const __nv_bfloat16* __restrict__ Wl,
        const float* __restrict__ bias, float* __restrict__ out, int mode) {
    extern __shared__ char smem[];
    u32 sb = smem_u32(smem);

    int tid = threadIdx.x;
    int lane = tid & 31;
    int wid = tid >> 5;       // 0..15
    int wm = wid & 3;         // 4 row groups of 32
    int wn = wid >> 2;        // 4 col groups of 32
    int bm = blockIdx.y * 128;
    int bn = blockIdx.x * 128;

    float acc[2][4][4];
#pragma unroll
    for (int i = 0; i < 2; i++)
#pragma unroll
        for (int j = 0; j < 4; j++)
#pragma unroll
            for (int r = 0; r < 4; r++) acc[i][j][r] = 0.f;

    // cp.async load of K-chunk c into stage s
    auto load_chunk = [&](int c, int s) {
        u32 st = sb + s * STAGE_BYTES;
        int c0 = c * KCH;
        // A: 128 rows x 64 halves = 1024 x 16B per array
#pragma unroll
        for (int u = tid; u < 1024; u += 512) {
            int row = u >> 3, seg = u & 7;
            size_t gofs = (size_t)(bm + row) * C_ + c0 + seg * 8;
            u32 dofs = (u32)(row * SA + seg * 8) * 2;
            CP_ASYNC16(st + AH_OFF + dofs, Ah + gofs);
            CP_ASYNC16(st + AL_OFF + dofs, Al + gofs);
        }
        // B: 64 rows x 128 halves = 1024 x 16B per array
#pragma unroll
        for (int u = tid; u < 1024; u += 512) {
            int row = u >> 4, seg = u & 15;
            size_t gofs = (size_t)(c0 + row) * C_ + bn + seg * 8;
            u32 dofs = (u32)(row * SB + seg * 8) * 2;
            CP_ASYNC16(st + BH_OFF + dofs, Wh + gofs);
            CP_ASYNC16(st + BL_OFF + dofs, Wl + gofs);
        }
        CP_COMMIT();
    };

    load_chunk(0, 0);

    int lr = lane & 15;
    int lh = lane >> 4;

    for (int c = 0; c < NCH; c++) {
        int s = c & 1;
        if (c + 1 < NCH) { load_chunk(c + 1, s ^ 1); CP_WAIT1(); }
        else             { CP_WAIT0(); }
        __syncthreads();

        u32 st = sb + s * STAGE_BYTES;
#pragma unroll
        for (int ks = 0; ks < 4; ks++) {
            int k0 = ks * 16;
            u32 ah[2][4], al[2][4];
#pragma unroll
            for (int mt = 0; mt < 2; mt++) {
                u32 arow = (u32)(wm * 32 + mt * 16 + lr);
                u32 aoff = (arow * SA + k0 + lh * 8) * 2;
                ldsm_x4(st + AH_OFF + aoff, ah[mt][0], ah[mt][1], ah[mt][2], ah[mt][3]);
                ldsm_x4(st + AL_OFF + aoff, al[mt][0], al[mt][1], al[mt][2], al[mt][3]);
            }
#pragma unroll
            for (int np = 0; np < 2; np++) {
                u32 brow = (u32)(k0 + lr);
                u32 bcol = (u32)(wn * 32 + np * 16 + lh * 8);
                u32 boff = (brow * SB + bcol) * 2;
                u32 bh0, bh1, bh2, bh3, bl0, bl1, bl2, bl3;
                ldsm_x4_t(st + BH_OFF + boff, bh0, bh1, bh2, bh3);
                ldsm_x4_t(st + BL_OFF + boff, bl0, bl1, bl2, bl3);
#pragma unroll
                for (int mt = 0; mt < 2; mt++) {
                    float* c0p = acc[mt][np * 2];
                    float* c1p = acc[mt][np * 2 + 1];
                    mma_bf16(c0p, ah[mt][0], ah[mt][1], ah[mt][2], ah[mt][3], bh0, bh1);
                    mma_bf16(c1p, ah[mt][0], ah[mt][1], ah[mt][2], ah[mt][3], bh2, bh3);
                    mma_bf16(c0p, ah[mt][0], ah[mt][1], ah[mt][2], ah[mt][3], bl0, bl1);
                    mma_bf16(c1p, ah[mt][0], ah[mt][1], ah[mt][2], ah[mt][3], bl2, bl3);
                    mma_bf16(c0p, al[mt][0], al[mt][1], al[mt][2], al[mt][3], bh0, bh1);
                    mma_bf16(c1p, al[mt][0], al[mt][1], al[mt][2], al[mt][3], bh2, bh3);
                }
            }
        }
        __syncthreads();
    }

    // Epilogue
    int rq = lane >> 2;
    int cq = (lane & 3) * 2;
#pragma unroll
    for (int mt = 0; mt < 2; mt++) {
#pragma unroll
        for (int nt = 0; nt < 4; nt++) {
            int gc = bn + wn * 32 + nt * 8 + cq;
            float b0 = bias[gc], b1 = bias[gc + 1];
#pragma unroll
            for (int half = 0; half < 2; half++) {
                int grow = bm + wm * 32 + mt * 16 + rq + half * 8;
                float2 o;
                o.x = acc[mt][nt][half * 2 + 0] + b0;
                o.y = acc[mt][nt][half * 2 + 1] + b1;
                float* op;
                if (mode == 0) {
                    op = out + (size_t)grow * C_ + gc;
                } else {
                    int h = gc >> 6, d0 = gc & 63;
                    int b = grow >> 11, t = grow & (T_ - 1);
                    op = out + (((size_t)b * H_ + h) * T_ + t) * D_ + d0;
                }
                *(float2*)op = o;
            }
        }
    }
}

__global__ __launch_bounds__(512, 1) void mma_qkv_kernel(
        const float* __restrict__ bq, const float* __restrict__ bk,
        const float* __restrict__ bv) {
    int z = blockIdx.z;
    const __nv_bfloat16* Wh = g_wh + (size_t)z * C_ * C_;
    const __nv_bfloat16* Wl = g_wl + (size_t)z * C_ * C_;
    const float* bias = z == 0 ? bq : z == 1 ? bk : bv;
    float* dst = z == 0 ? g_q : z == 1 ? g_k : g_v;
    hmma_gemm_body(g_xh, g_xl, Wh, Wl, bias, dst, 1);
}

__global__ __launch_bounds__(512, 1) void mma_proj_kernel(
        const float* __restrict__ bp, float* __restrict__ out) {
    hmma_gemm_body(g_yh, g_yl, g_wh + 3 * (size_t)C_ * C_,
                   g_wl + 3 * (size_t)C_ * C_, bp, out, 0);
}

// ---------------------------------------------------------------------------
// Rope + bf16 hi/lo split. seg 0: q (rotate + 1/8 scale), 1: k (rotate), 2: v
// ---------------------------------------------------------------------------
__global__ void rope_split_kernel() {
    const int NH = B_ * H_ * T_ * 32;
    int idx = blockIdx.x * 256 + threadIdx.x;
    int seg = idx / NH;
    int r = idx - seg * NH;
    int d = r & 31;
    int row = r >> 5;
    int t = row & (T_ - 1);
    size_t p = ((size_t)row << 6) + d;

    float y1, y2;
    __nv_bfloat16 *oh, *ol;
    if (seg == 0) {
        float c = g_cos[(t << 6) + d], s = g_sin[(t << 6) + d];
        float x1 = g_q[p], x2 = g_q[p + 32];
        y1 = (x1 * c - x2 * s) * 0.125f;
        y2 = (x2 * c + x1 * s) * 0.125f;
        oh = g_qbh; ol = g_qbl;
    } else if (seg == 1) {
        float c = g_cos[(t << 6) + d], s = g_sin[(t << 6) + d];
        float x1 = g_k[p], x2 = g_k[p + 32];
        y1 = x1 * c - x2 * s;
        y2 = x2 * c + x1 * s;
        oh = g_kbh; ol = g_kbl;
    } else {
        y1 = g_v[p]; y2 = g_v[p + 32];
        oh = g_vbh; ol = g_vbl;
    }
    __nv_bfloat16 h1, l1, h2, l2;
    split1(y1, h1, l1); split1(y2, h2, l2);
    oh[p] = h1; oh[p + 32] = h2;
    ol[p] = l1; ol[p + 32] = l2;
}

// ---------------------------------------------------------------------------
// HMMA flash attention (unchanged from R5). CTA: 128 queries x one (b,h).
// ---------------------------------------------------------------------------
#define AST 72
#define KV_ARRB (64 * AST * 2)
#define KV_STAGEB (4 * KV_ARRB)
#define AT_SMEM (2 * KV_STAGEB + T_ * 4)

__global__ __launch_bounds__(256, 1) void attn_mma_kernel() {
    extern __shared__ char asm_[];
    u32 sbase = smem_u32(asm_);
    float* sbias = (float*)(asm_ + 2 * KV_STAGEB);
    __nv_bfloat16* sst = (__nv_bfloat16*)asm_;

    int bh = blockIdx.y;
    int h = bh & (H_ - 1);
    int qb = gridDim.x - 1 - blockIdx.x;
    int q0 = qb * 128;
    int tid = threadIdx.x;
    int lane = tid & 31;
    int w = tid >> 5;
    int qw = q0 + w * 16;

    const __nv_bfloat16* qbh = g_qbh + ((size_t)bh * T_ + q0) * D_;
    const __nv_bfloat16* qbl = g_qbl + ((size_t)bh * T_ + q0) * D_;
    size_t kvo = (size_t)bh * T_ * D_;

    {
        const float4* b4 = (const float4*)(g_bias + h * T_);
        for (int i = tid; i < T_ / 4; i += 256) {
            float4 v = b4[i];
            v.x *= 0.125f; v.y *= 0.125f; v.z *= 0.125f; v.w *= 0.125f;
            ((float4*)sbias)[i] = v;
        }
    }
    for (int u = tid; u < 1024; u += 256) {
        int row = u >> 3, seg = u & 7;
        *(uint4*)(sst + row * AST + seg * 8) =
            *(const uint4*)(qbh + row * 64 + seg * 8);
        *(uint4*)(sst + 128 * AST + row * AST + seg * 8) =
            *(const uint4*)(qbl + row * 64 + seg * 8);
    }
    __syncthreads();

    u32 qfh[4][4], qfl[4][4];
    {
        int lr = lane & 15, lh = lane >> 4;
#pragma unroll
        for (int kc = 0; kc < 4; kc++) {
            u32 off = (u32)((w * 16 + lr) * AST + kc * 16 + lh * 8) * 2;
            ldsm_x4(sbase + off, qfh[kc][0], qfh[kc][1], qfh[kc][2], qfh[kc][3]);
            ldsm_x4(sbase + 128 * AST * 2 + off, qfl[kc][0], qfl[kc][1], qfl[kc][2], qfl[kc][3]);
        }
    }
    __syncthreads();

    auto load_kv = [&](int blk, int s) {
        u32 st = sbase + s * KV_STAGEB;
        const __nv_bfloat16* kh = g_kbh + kvo + (size_t)blk * 64 * 64;
        const __nv_bfloat16* kl = g_kbl + kvo + (size_t)blk * 64 * 64;
        const __nv_bfloat16* vh = g_vbh + kvo + (size_t)blk * 64 * 64;
        const __nv_bfloat16* vl = g_vbl + kvo + (size_t)blk * 64 * 64;
#pragma unroll
        for (int u = tid; u < 512; u += 256) {
            int row = u >> 3, seg = u & 7;
            u32 doff = (u32)(row * AST + seg * 8) * 2;
            int goff = row * 64 + seg * 8;
            CP_ASYNC16(st + doff,              kh + goff);
            CP_ASYNC16(st + KV_ARRB + doff,    kl + goff);
            CP_ASYNC16(st + 2*KV_ARRB + doff,  vh + goff);
            CP_ASYNC16(st + 3*KV_ARRB + doff,  vl + goff);
        }
        CP_COMMIT();
    };

    int nblk = q0 / 64 + 2;
    load_kv(0, 0);

    float mlo = -CUDART_INF_F, mhi = -CUDART_INF_F;
    float llo = 0.f, lhi = 0.f;
    float oacc[8][4];
#pragma unroll
    for (int i = 0; i < 8; i++)
#pragma unroll
        for (int j = 0; j < 4; j++) oacc[i][j] = 0.f;

    int rlo = qw + (lane >> 2);
    int rhi = rlo + 8;
    int cq = (lane & 3) * 2;

    for (int blk = 0; blk < nblk; blk++) {
        int s = blk & 1;
        if (blk + 1 < nblk) { load_kv(blk + 1, s ^ 1); CP_WAIT1(); }
        else                { CP_WAIT0(); }
        __syncthreads();

        int j0 = blk * 64;
        if (j0 <= qw + 15) {
            u32 st = sbase + s * KV_STAGEB;
            int lr = lane & 15, lh = lane >> 4;

            float sacc[8][4];
#pragma unroll
            for (int i = 0; i < 8; i++)
#pragma unroll
                for (int j = 0; j < 4; j++) sacc[i][j] = 0.f;
#pragma unroll
            for (int kg = 0; kg < 4; kg++) {
#pragma unroll
                for (int kc = 0; kc < 4; kc++) {
                    u32 off = (u32)((kg * 16 + lr) * AST + kc * 16 + lh * 8) * 2;
                    u32 kh0, kh1, kh2, kh3, kl0, kl1, kl2, kl3;
                    ldsm_x4(st + off, kh0, kh1, kh2, kh3);
                    ldsm_x4(st + KV_ARRB + off, kl0, kl1, kl2, kl3);
                    float* e = sacc[2 * kg];
                    float* o = sacc[2 * kg + 1];
                    mma_bf16(e, qfh[kc][0], qfh[kc][1], qfh[kc][2], qfh[kc][3], kh0, kh2);
                    mma_bf16(o, qfh[kc][0], qfh[kc][1], qfh[kc][2], qfh[kc][3], kh1, kh3);
                    mma_bf16(e, qfh[kc][0], qfh[kc][1], qfh[kc][2], qfh[kc][3], kl0, kl2);
                    mma_bf16(o, qfh[kc][0], qfh[kc][1], qfh[kc][2], qfh[kc][3], kl1, kl3);
                    mma_bf16(e, qfl[kc][0], qfl[kc][1], qfl[kc][2], qfl[kc][3], kh0, kh2);
                    mma_bf16(o, qfl[kc][0], qfl[kc][1], qfl[kc][2], qfl[kc][3], kh1, kh3);
                }
            }

#pragma unroll
            for (int nf = 0; nf < 8; nf++) {
                int jc = j0 + nf * 8 + cq;
                int d0 = rlo - jc;
                int d2 = rhi - jc;
                sacc[nf][0] = (d0 >= 0) ? sacc[nf][0] + sbias[d0]     : -CUDART_INF_F;
                sacc[nf][1] = (d0 >= 1) ? sacc[nf][1] + sbias[d0 - 1] : -CUDART_INF_F;
                sacc[nf][2] = (d2 >= 0) ? sacc[nf][2] + sbias[d2]     : -CUDART_INF_F;
                sacc[nf][3] = (d2 >= 1) ? sacc[nf][3] + sbias[d2 - 1] : -CUDART_INF_F;
            }

            float bmlo = sacc[0][0], bmhi = sacc[0][2];
#pragma unroll
            for (int nf = 0; nf < 8; nf++) {
                bmlo = fmaxf(bmlo, fmaxf(sacc[nf][0], sacc[nf][1]));
                bmhi = fmaxf(bmhi, fmaxf(sacc[nf][2], sacc[nf][3]));
            }
            bmlo = fmaxf(bmlo, __shfl_xor_sync(0xffffffffu, bmlo, 1));
            bmlo = fmaxf(bmlo, __shfl_xor_sync(0xffffffffu, bmlo, 2));
            bmhi = fmaxf(bmhi, __shfl_xor_sync(0xffffffffu, bmhi, 1));
            bmhi = fmaxf(bmhi, __shfl_xor_sync(0xffffffffu, bmhi, 2));

            float nmlo = fmaxf(mlo, bmlo), nmhi = fmaxf(mhi, bmhi);
            float clo = __expf(mlo - nmlo), chi = __expf(mhi - nmhi);
            mlo = nmlo; mhi = nmhi;
            llo *= clo; lhi *= chi;
#pragma unroll
            for (int nf = 0; nf < 8; nf++) {
                oacc[nf][0] *= clo; oacc[nf][1] *= clo;
                oacc[nf][2] *= chi; oacc[nf][3] *= chi;
            }

            u32 pfh[4][4], pfl[4][4];
#pragma unroll
            for (int nf = 0; nf < 8; nf++) {
                float p0 = __expf(sacc[nf][0] - mlo);
                float p1 = __expf(sacc[nf][1] - mlo);
                float p2 = __expf(sacc[nf][2] - mhi);
                float p3 = __expf(sacc[nf][3] - mhi);
                llo += p0 + p1;
                lhi += p2 + p3;
                __nv_bfloat16 h0, l0, h1, l1, h2, l2, h3, l3;
                split1(p0, h0, l0); split1(p1, h1, l1);
                split1(p2, h2, l2); split1(p3, h3, l3);
                int kc = nf >> 1, half = nf & 1;
                pfh[kc][half * 2 + 0] = pack_bf16(__bfloat162float(h0), __bfloat162float(h1));
                pfh[kc][half * 2 + 1] = pack_bf16(__bfloat162float(h2), __bfloat162float(h3));
                pfl[kc][half * 2 + 0] = pack_bf16(__bfloat162float(l0), __bfloat162float(l1));
                pfl[kc][half * 2 + 1] = pack_bf16(__bfloat162float(l2), __bfloat162float(l3));
            }

#pragma unroll
            for (int dg = 0; dg < 4; dg++) {
#pragma unroll
                for (int kc = 0; kc < 4; kc++) {
                    u32 off = (u32)((kc * 16 + lr) * AST + dg * 16 + lh * 8) * 2;
                    u32 vh0, vh1, vh2, vh3, vl0, vl1, vl2, vl3;
                    ldsm_x4_t(st + 2*KV_ARRB + off, vh0, vh1, vh2, vh3);
                    ldsm_x4_t(st + 3*KV_ARRB + off, vl0, vl1, vl2, vl3);
                    float* e = oacc[2 * dg];
                    float* o = oacc[2 * dg + 1];
                    mma_bf16(e, pfh[kc][0], pfh[kc][1], pfh[kc][2], pfh[kc][3], vh0, vh1);
                    mma_bf16(o, pfh[kc][0], pfh[kc][1], pfh[kc][2], pfh[kc][3], vh2, vh3);
                    mma_bf16(e, pfh[kc][0], pfh[kc][1], pfh[kc][2], pfh[kc][3], vl0, vl1);
                    mma_bf16(o, pfh[kc][0], pfh[kc][1], pfh[kc][2], pfh[kc][3], vl2, vl3);
                    mma_bf16(e, pfl[kc][0], pfl[kc][1], pfl[kc][2], pfl[kc][3], vh0, vh1);
                    mma_bf16(o, pfl[kc][0], pfl[kc][1], pfl[kc][2], pfl[kc][3], vh2, vh3);
                }
            }
        }
        __syncthreads();
    }

    llo += __shfl_xor_sync(0xffffffffu, llo, 1);
    llo += __shfl_xor_sync(0xffffffffu, llo, 2);
    lhi += __shfl_xor_sync(0xffffffffu, lhi, 1);
    lhi += __shfl_xor_sync(0xffffffffu, lhi, 2);
    float ilo = 1.f / llo, ihi = 1.f / lhi;

    int b = bh >> 4;
    float* ylo = g_y + ((size_t)b * T_ + rlo) * C_ + h * D_ + cq;
    float* yhi = g_y + ((size_t)b * T_ + rhi) * C_ + h * D_ + cq;
#pragma unroll
    for (int nf = 0; nf < 8; nf++) {
        *(float2*)(ylo + nf * 8) = make_float2(oacc[nf][0] * ilo, oacc[nf][1] * ilo);
        *(float2*)(yhi + nf * 8) = make_float2(oacc[nf][2] * ihi, oacc[nf][3] * ihi);
    }
}

// ---------------------------------------------------------------------------
extern "C" void kernel_launch(void* const* d_in, const int* in_sizes, int n_in,
                              void* d_out, int out_size) {
    const float* x   = (const float*)d_in[0];
    const float* Wq  = (const float*)d_in[1];
    const float* bq  = (const float*)d_in[2];
    const float* Wk  = (const float*)d_in[3];
    const float* bk  = (const float*)d_in[4];
    const float* Wv  = (const float*)d_in[5];
    const float* bv  = (const float*)d_in[6];
    const float* Wp  = (const float*)d_in[7];
    const float* bp  = (const float*)d_in[8];
    const float* tbl = (const float*)d_in[9];
    float* out = (float*)d_out;

    cudaFuncSetAttribute(mma_qkv_kernel,
                         cudaFuncAttributeMaxDynamicSharedMemorySize, SMEM_TOTAL);
    cudaFuncSetAttribute(mma_proj_kernel,
                         cudaFuncAttributeMaxDynamicSharedMemorySize, SMEM_TOTAL);
    cudaFuncSetAttribute(attn_mma_kernel,
                         cudaFuncAttributeMaxDynamicSharedMemorySize, AT_SMEM);

    tables_kernel<<<(T_ * D_ + 255) / 256, 256>>>(tbl);
    split_act_kernel<<<(B_ * T_ * C_ / 4) / 256, 256>>>(x, 0);
    split_w_kernel<<<dim3((C_ * C_ / 4) / 256, 4), 256>>>(Wq, Wk, Wv, Wp);

    mma_qkv_kernel<<<dim3(C_ / 128, (B_ * T_) / 128, 3), 512, SMEM_TOTAL>>>(bq, bk, bv);

    rope_split_kernel<<<(3 * B_ * H_ * T_ * 32) / 256, 256>>>();

    attn_mma_kernel<<<dim3(T_ / 128, B_ * H_), 256, AT_SMEM>>>();

    split_act_kernel<<<(B_ * T_ * C_ / 4) / 256, 256>>>(nullptr, 1);
    mma_proj_kernel<<<dim3(C_ / 128, (B_ * T_) / 128), 512, SMEM_TOTAL>>>(bp, out);
}

// round 8
// speedup vs baseline: 4.9975x; 1.4492x over previous
#include <cuda_runtime.h>
#include <cuda_fp16.h>
#include <math.h>
#include <math_constants.h>

#define B_  2
#define T_  2048
#define C_  1024
#define H_  16
#define D_  64
#define KCH 64               // GEMM K elems per pipeline chunk
#define NCH (C_ / KCH)       // 16 chunks

typedef unsigned int u32;

// ---------------------------------------------------------------------------
// Scratch (__device__ globals: allocation-free rule)
// ---------------------------------------------------------------------------
static __device__ __align__(16) float g_q[(size_t)B_*H_*T_*D_];
static __device__ __align__(16) float g_k[(size_t)B_*H_*T_*D_];
static __device__ __align__(16) float g_v[(size_t)B_*H_*T_*D_];
static __device__ __align__(16) float g_y[(size_t)B_*T_*C_];
static __device__ __align__(16) float g_bias[H_*T_];
static __device__ __align__(16) float g_cos[T_*D_];
static __device__ __align__(16) float g_sin[T_*D_];
// fp16 operands for GEMMs: activations split hi/lo, weights single
static __device__ __align__(16) __half g_xh[(size_t)B_*T_*C_];
static __device__ __align__(16) __half g_xl[(size_t)B_*T_*C_];
static __device__ __align__(16) __half g_yh[(size_t)B_*T_*C_];
static __device__ __align__(16) __half g_yl[(size_t)B_*T_*C_];
static __device__ __align__(16) __half g_w[4 * (size_t)C_*C_];
// fp16 operands for attention (head layout [B,H,T,D])
static __device__ __align__(16) __half g_qf[(size_t)B_*H_*T_*D_];   // single
static __device__ __align__(16) __half g_kf[(size_t)B_*H_*T_*D_];   // single
static __device__ __align__(16) __half g_vfh[(size_t)B_*H_*T_*D_];  // V hi
static __device__ __align__(16) __half g_vfl[(size_t)B_*H_*T_*D_];  // V lo

// ---------------------------------------------------------------------------
// Baseline-PTX helpers (sm_80-compatible: ldmatrix / mma.sync / cp.async)
// ---------------------------------------------------------------------------
__device__ __forceinline__ u32 smem_u32(const void* p) {
    u32 a;
    asm("{ .reg .u64 t; cvta.to.shared.u64 t, %1; cvt.u32.u64 %0, t; }" : "=r"(a) : "l"(p));
    return a;
}
__device__ __forceinline__ void ldsm_x4(u32 addr, u32& r0, u32& r1, u32& r2, u32& r3) {
    asm volatile("ldmatrix.sync.aligned.m8n8.x4.shared.b16 {%0,%1,%2,%3}, [%4];"
                 : "=r"(r0), "=r"(r1), "=r"(r2), "=r"(r3) : "r"(addr));
}
__device__ __forceinline__ void ldsm_x4_t(u32 addr, u32& r0, u32& r1, u32& r2, u32& r3) {
    asm volatile("ldmatrix.sync.aligned.m8n8.x4.trans.shared.b16 {%0,%1,%2,%3}, [%4];"
                 : "=r"(r0), "=r"(r1), "=r"(r2), "=r"(r3) : "r"(addr));
}
__device__ __forceinline__ void mma_f16(float* c, u32 a0, u32 a1, u32 a2, u32 a3,
                                        u32 b0, u32 b1) {
    asm volatile("mma.sync.aligned.m16n8k16.row.col.f32.f16.f16.f32 "
                 "{%0,%1,%2,%3}, {%4,%5,%6,%7}, {%8,%9}, {%0,%1,%2,%3};"
                 : "+f"(c[0]), "+f"(c[1]), "+f"(c[2]), "+f"(c[3])
                 : "r"(a0), "r"(a1), "r"(a2), "r"(a3), "r"(b0), "r"(b1));
}
#define CP_ASYNC16(dst, src) \
    asm volatile("cp.async.cg.shared.global [%0], [%1], 16;" :: "r"(dst), "l"(src))
#define CP_COMMIT() asm volatile("cp.async.commit_group;" ::: "memory")
#define CP_WAIT1()  asm volatile("cp.async.wait_group 1;" ::: "memory")
#define CP_WAIT0()  asm volatile("cp.async.wait_group 0;" ::: "memory")

__device__ __forceinline__ u32 pack_f16(float lo, float hi) {
    __half2 h = __floats2half2_rn(lo, hi);
    return *(u32*)&h;
}

// ---------------------------------------------------------------------------
// Tables
// ---------------------------------------------------------------------------
__global__ void tables_kernel(const float* __restrict__ rel_table) {
    int idx = blockIdx.x * blockDim.x + threadIdx.x;
    if (idx < T_ * D_) {
        int t = idx >> 6;
        int d = idx & 63;
        int j = d & 31;
        float inv = (float)pow(10000.0, -(double)(2 * j) / 64.0);
        float fr = (float)t * inv;
        g_cos[idx] = cosf(fr);
        g_sin[idx] = sinf(fr);
    }
    if (idx < H_ * T_) {
        int h = idx / T_;
        int n = idx % T_;
        int bucket;
        if (n < 16) {
            bucket = n;
        } else {
            float v = logf((float)n * (1.0f / 16.0f)) / 2.0794415416798357f * 16.0f;
            bucket = 16 + (int)v;
            if (bucket > 31) bucket = 31;
        }
        g_bias[idx] = rel_table[bucket * H_ + h];
    }
}

// ---------------------------------------------------------------------------
// fp32 -> fp16 hi/lo split
// ---------------------------------------------------------------------------
__device__ __forceinline__ void split1h(float v, __half& h, __half& l) {
    h = __float2half_rn(v);
    l = __float2half_rn(v - __half2float(h));
}

__global__ void split_act_kernel(const float* __restrict__ xin, int which) {
    const float* src = which == 0 ? xin : g_y;
    __half* oh = which == 0 ? g_xh : g_yh;
    __half* ol = which == 0 ? g_xl : g_yl;
    int i = blockIdx.x * 256 + threadIdx.x;
    float4 v = ((const float4*)src)[i];
    __half h0, h1, h2, h3, l0, l1, l2, l3;
    split1h(v.x, h0, l0); split1h(v.y, h1, l1);
    split1h(v.z, h2, l2); split1h(v.w, h3, l3);
    ((__half2*)oh)[i * 2 + 0] = __half2(h0, h1);
    ((__half2*)oh)[i * 2 + 1] = __half2(h2, h3);
    ((__half2*)ol)[i * 2 + 0] = __half2(l0, l1);
    ((__half2*)ol)[i * 2 + 1] = __half2(l2, l3);
}

__global__ void split_w_kernel(const float* __restrict__ Wq, const float* __restrict__ Wk,
                               const float* __restrict__ Wv, const float* __restrict__ Wp) {
    int z = blockIdx.y;
    const float* W = z == 0 ? Wq : z == 1 ? Wk : z == 2 ? Wv : Wp;
    __half* ow = g_w + (size_t)z * C_ * C_;
    int i = blockIdx.x * 256 + threadIdx.x;
    float4 v = ((const float4*)W)[i];
    ((__half2*)ow)[i * 2 + 0] = __floats2half2_rn(v.x, v.y);
    ((__half2*)ow)[i * 2 + 1] = __floats2half2_rn(v.z, v.w);
}

// ---------------------------------------------------------------------------
// HMMA GEMM v3: A split fp16 hi/lo x W single fp16 (2 products).
// 128x128 CTA, 512 threads (16 warps 4x4, warp tile 32x32), K chunks of 64.
// mode 0: row-major out; mode 1: head layout [B,H,T,D].
// ---------------------------------------------------------------------------
#define SA 72        // A smem row stride (halves)
#define SB 136       // B smem row stride (halves)
#define AH_OFF 0
#define AL_OFF (128 * SA * 2)                     // 18432
#define B_OFF  (2 * 128 * SA * 2)                 // 36864
#define STAGE_BYTES (B_OFF + KCH * SB * 2)        // 54272
#define SMEM_TOTAL (2 * STAGE_BYTES)              // 108544

__device__ __forceinline__ void hmma_gemm_body(
        const __half* __restrict__ Ah, const __half* __restrict__ Al,
        const __half* __restrict__ Wf,
        const float* __restrict__ bias, float* __restrict__ out, int mode) {
    extern __shared__ char smem[];
    u32 sb = smem_u32(smem);

    int tid = threadIdx.x;
    int lane = tid & 31;
    int wid = tid >> 5;
    int wm = wid & 3;
    int wn = wid >> 2;
    int bm = blockIdx.y * 128;
    int bn = blockIdx.x * 128;

    float acc[2][4][4];
#pragma unroll
    for (int i = 0; i < 2; i++)
#pragma unroll
        for (int j = 0; j < 4; j++)
#pragma unroll
            for (int r = 0; r < 4; r++) acc[i][j][r] = 0.f;

    auto load_chunk = [&](int c, int s) {
        u32 st = sb + s * STAGE_BYTES;
        int c0 = c * KCH;
#pragma unroll
        for (int u = tid; u < 1024; u += 512) {
            int row = u >> 3, seg = u & 7;
            size_t gofs = (size_t)(bm + row) * C_ + c0 + seg * 8;
            u32 dofs = (u32)(row * SA + seg * 8) * 2;
            CP_ASYNC16(st + AH_OFF + dofs, Ah + gofs);
            CP_ASYNC16(st + AL_OFF + dofs, Al + gofs);
        }
#pragma unroll
        for (int u = tid; u < 1024; u += 512) {
            int row = u >> 4, seg = u & 15;
            size_t gofs = (size_t)(c0 + row) * C_ + bn + seg * 8;
            u32 dofs = (u32)(row * SB + seg * 8) * 2;
            CP_ASYNC16(st + B_OFF + dofs, Wf + gofs);
        }
        CP_COMMIT();
    };

    load_chunk(0, 0);

    int lr = lane & 15;
    int lh = lane >> 4;

    for (int c = 0; c < NCH; c++) {
        int s = c & 1;
        if (c + 1 < NCH) { load_chunk(c + 1, s ^ 1); CP_WAIT1(); }
        else             { CP_WAIT0(); }
        __syncthreads();

        u32 st = sb + s * STAGE_BYTES;
#pragma unroll
        for (int ks = 0; ks < 4; ks++) {
            int k0 = ks * 16;
            u32 ah[2][4], al[2][4];
#pragma unroll
            for (int mt = 0; mt < 2; mt++) {
                u32 arow = (u32)(wm * 32 + mt * 16 + lr);
                u32 aoff = (arow * SA + k0 + lh * 8) * 2;
                ldsm_x4(st + AH_OFF + aoff, ah[mt][0], ah[mt][1], ah[mt][2], ah[mt][3]);
                ldsm_x4(st + AL_OFF + aoff, al[mt][0], al[mt][1], al[mt][2], al[mt][3]);
            }
#pragma unroll
            for (int np = 0; np < 2; np++) {
                u32 brow = (u32)(k0 + lr);
                u32 bcol = (u32)(wn * 32 + np * 16 + lh * 8);
                u32 boff = (brow * SB + bcol) * 2;
                u32 b0, b1, b2, b3;
                ldsm_x4_t(st + B_OFF + boff, b0, b1, b2, b3);
#pragma unroll
                for (int mt = 0; mt < 2; mt++) {
                    float* c0p = acc[mt][np * 2];
                    float* c1p = acc[mt][np * 2 + 1];
                    mma_f16(c0p, ah[mt][0], ah[mt][1], ah[mt][2], ah[mt][3], b0, b1);
                    mma_f16(c1p, ah[mt][0], ah[mt][1], ah[mt][2], ah[mt][3], b2, b3);
                    mma_f16(c0p, al[mt][0], al[mt][1], al[mt][2], al[mt][3], b0, b1);
                    mma_f16(c1p, al[mt][0], al[mt][1], al[mt][2], al[mt][3], b2, b3);
                }
            }
        }
        __syncthreads();
    }

    int rq = lane >> 2;
    int cq = (lane & 3) * 2;
#pragma unroll
    for (int mt = 0; mt < 2; mt++) {
#pragma unroll
        for (int nt = 0; nt < 4; nt++) {
            int gc = bn + wn * 32 + nt * 8 + cq;
            float b0 = bias[gc], b1 = bias[gc + 1];
#pragma unroll
            for (int half = 0; half < 2; half++) {
                int grow = bm + wm * 32 + mt * 16 + rq + half * 8;
                float2 o;
                o.x = acc[mt][nt][half * 2 + 0] + b0;
                o.y = acc[mt][nt][half * 2 + 1] + b1;
                float* op;
                if (mode == 0) {
                    op = out + (size_t)grow * C_ + gc;
                } else {
                    int h = gc >> 6, d0 = gc & 63;
                    int b = grow >> 11, t = grow & (T_ - 1);
                    op = out + (((size_t)b * H_ + h) * T_ + t) * D_ + d0;
                }
                *(float2*)op = o;
            }
        }
    }
}

__global__ __launch_bounds__(512, 1) void mma_qkv_kernel(
        const float* __restrict__ bq, const float* __restrict__ bk,
        const float* __restrict__ bv) {
    int z = blockIdx.z;
    const __half* Wf = g_w + (size_t)z * C_ * C_;
    const float* bias = z == 0 ? bq : z == 1 ? bk : bv;
    float* dst = z == 0 ? g_q : z == 1 ? g_k : g_v;
    hmma_gemm_body(g_xh, g_xl, Wf, bias, dst, 1);
}

__global__ __launch_bounds__(512, 1) void mma_proj_kernel(
        const float* __restrict__ bp, float* __restrict__ out) {
    hmma_gemm_body(g_yh, g_yl, g_w + 3 * (size_t)C_ * C_, bp, out, 0);
}

// ---------------------------------------------------------------------------
// Rope + fp16 convert. seg 0: q (rotate + 1/8, single), 1: k (rotate, single),
// 2: v (split hi/lo)
// ---------------------------------------------------------------------------
__global__ void rope_split_kernel() {
    const int NH = B_ * H_ * T_ * 32;
    int idx = blockIdx.x * 256 + threadIdx.x;
    int seg = idx / NH;
    int r = idx - seg * NH;
    int d = r & 31;
    int row = r >> 5;
    int t = row & (T_ - 1);
    size_t p = ((size_t)row << 6) + d;

    if (seg == 0) {
        float c = g_cos[(t << 6) + d], s = g_sin[(t << 6) + d];
        float x1 = g_q[p], x2 = g_q[p + 32];
        g_qf[p]      = __float2half_rn((x1 * c - x2 * s) * 0.125f);
        g_qf[p + 32] = __float2half_rn((x2 * c + x1 * s) * 0.125f);
    } else if (seg == 1) {
        float c = g_cos[(t << 6) + d], s = g_sin[(t << 6) + d];
        float x1 = g_k[p], x2 = g_k[p + 32];
        g_kf[p]      = __float2half_rn(x1 * c - x2 * s);
        g_kf[p + 32] = __float2half_rn(x2 * c + x1 * s);
    } else {
        __half h1, l1, h2, l2;
        split1h(g_v[p], h1, l1);
        split1h(g_v[p + 32], h2, l2);
        g_vfh[p] = h1; g_vfh[p + 32] = h2;
        g_vfl[p] = l1; g_vfl[p + 32] = l2;
    }
}

// ---------------------------------------------------------------------------
// HMMA flash attention v2: QK 1-product (Q,K single fp16), PV 2-product
// (P single fp16, V split hi/lo). CTA: 128 queries x one (b,h), 8 warps.
// ---------------------------------------------------------------------------
#define AST 72
#define KV_ARRB (64 * AST * 2)               // 9216
#define KV_STAGEB (3 * KV_ARRB)              // 27648 (K, Vh, Vl)
#define AT_SMEM (2 * KV_STAGEB + T_ * 4)     // 63488

__global__ __launch_bounds__(256, 1) void attn_mma_kernel() {
    extern __shared__ char asm_[];
    u32 sbase = smem_u32(asm_);
    float* sbias = (float*)(asm_ + 2 * KV_STAGEB);
    __half* sst = (__half*)asm_;

    int bh = blockIdx.y;
    int h = bh & (H_ - 1);
    int qb = gridDim.x - 1 - blockIdx.x;
    int q0 = qb * 128;
    int tid = threadIdx.x;
    int lane = tid & 31;
    int w = tid >> 5;
    int qw = q0 + w * 16;

    const __half* qf = g_qf + ((size_t)bh * T_ + q0) * D_;
    size_t kvo = (size_t)bh * T_ * D_;

    {
        const float4* b4 = (const float4*)(g_bias + h * T_);
        for (int i = tid; i < T_ / 4; i += 256) {
            float4 v = b4[i];
            v.x *= 0.125f; v.y *= 0.125f; v.z *= 0.125f; v.w *= 0.125f;
            ((float4*)sbias)[i] = v;
        }
    }
    // stage Q (single, 128x64 fp16) into stage-0 area  [FIXED: 8-half segs]
    for (int u = tid; u < 1024; u += 256) {
        int row = u >> 3, seg = u & 7;
        *(uint4*)(sst + row * AST + seg * 8) =
            *(const uint4*)(qf + row * 64 + seg * 8);
    }
    __syncthreads();

    u32 qfr[4][4];
    {
        int lr = lane & 15, lh = lane >> 4;
#pragma unroll
        for (int kc = 0; kc < 4; kc++) {
            u32 off = (u32)((w * 16 + lr) * AST + kc * 16 + lh * 8) * 2;
            ldsm_x4(sbase + off, qfr[kc][0], qfr[kc][1], qfr[kc][2], qfr[kc][3]);
        }
    }
    __syncthreads();

    auto load_kv = [&](int blk, int s) {
        u32 st = sbase + s * KV_STAGEB;
        const __half* kf = g_kf  + kvo + (size_t)blk * 64 * 64;
        const __half* vh = g_vfh + kvo + (size_t)blk * 64 * 64;
        const __half* vl = g_vfl + kvo + (size_t)blk * 64 * 64;
#pragma unroll
        for (int u = tid; u < 512; u += 256) {
            int row = u >> 3, seg = u & 7;
            u32 doff = (u32)(row * AST + seg * 8) * 2;
            int goff = row * 64 + seg * 8;
            CP_ASYNC16(st + doff,             kf + goff);
            CP_ASYNC16(st + KV_ARRB + doff,   vh + goff);
            CP_ASYNC16(st + 2*KV_ARRB + doff, vl + goff);
        }
        CP_COMMIT();
    };

    int nblk = q0 / 64 + 2;
    load_kv(0, 0);

    float mlo = -CUDART_INF_F, mhi = -CUDART_INF_F;
    float llo = 0.f, lhi = 0.f;
    float oacc[8][4];
#pragma unroll
    for (int i = 0; i < 8; i++)
#pragma unroll
        for (int j = 0; j < 4; j++) oacc[i][j] = 0.f;

    int rlo = qw + (lane >> 2);
    int rhi = rlo + 8;
    int cq = (lane & 3) * 2;

    for (int blk = 0; blk < nblk; blk++) {
        int s = blk & 1;
        if (blk + 1 < nblk) { load_kv(blk + 1, s ^ 1); CP_WAIT1(); }
        else                { CP_WAIT0(); }
        __syncthreads();

        int j0 = blk * 64;
        if (j0 <= qw + 15) {
            u32 st = sbase + s * KV_STAGEB;
            int lr = lane & 15, lh = lane >> 4;

            // S = Q K^T (1 product)
            float sacc[8][4];
#pragma unroll
            for (int i = 0; i < 8; i++)
#pragma unroll
                for (int j = 0; j < 4; j++) sacc[i][j] = 0.f;
#pragma unroll
            for (int kg = 0; kg < 4; kg++) {
#pragma unroll
                for (int kc = 0; kc < 4; kc++) {
                    u32 off = (u32)((kg * 16 + lr) * AST + kc * 16 + lh * 8) * 2;
                    u32 k0, k1, k2, k3;
                    ldsm_x4(st + off, k0, k1, k2, k3);
                    mma_f16(sacc[2 * kg],     qfr[kc][0], qfr[kc][1], qfr[kc][2], qfr[kc][3], k0, k2);
                    mma_f16(sacc[2 * kg + 1], qfr[kc][0], qfr[kc][1], qfr[kc][2], qfr[kc][3], k1, k3);
                }
            }

            // bias + causal mask
#pragma unroll
            for (int nf = 0; nf < 8; nf++) {
                int jc = j0 + nf * 8 + cq;
                int d0 = rlo - jc;
                int d2 = rhi - jc;
                sacc[nf][0] = (d0 >= 0) ? sacc[nf][0] + sbias[d0]     : -CUDART_INF_F;
                sacc[nf][1] = (d0 >= 1) ? sacc[nf][1] + sbias[d0 - 1] : -CUDART_INF_F;
                sacc[nf][2] = (d2 >= 0) ? sacc[nf][2] + sbias[d2]     : -CUDART_INF_F;
                sacc[nf][3] = (d2 >= 1) ? sacc[nf][3] + sbias[d2 - 1] : -CUDART_INF_F;
            }

            // row max
            float bmlo = sacc[0][0], bmhi = sacc[0][2];
#pragma unroll
            for (int nf = 0; nf < 8; nf++) {
                bmlo = fmaxf(bmlo, fmaxf(sacc[nf][0], sacc[nf][1]));
                bmhi = fmaxf(bmhi, fmaxf(sacc[nf][2], sacc[nf][3]));
            }
            bmlo = fmaxf(bmlo, __shfl_xor_sync(0xffffffffu, bmlo, 1));
            bmlo = fmaxf(bmlo, __shfl_xor_sync(0xffffffffu, bmlo, 2));
            bmhi = fmaxf(bmhi, __shfl_xor_sync(0xffffffffu, bmhi, 1));
            bmhi = fmaxf(bmhi, __shfl_xor_sync(0xffffffffu, bmhi, 2));

            float nmlo = fmaxf(mlo, bmlo), nmhi = fmaxf(mhi, bmhi);
            float clo = __expf(mlo - nmlo), chi = __expf(mhi - nmhi);
            mlo = nmlo; mhi = nmhi;
            llo *= clo; lhi *= chi;
#pragma unroll
            for (int nf = 0; nf < 8; nf++) {
                oacc[nf][0] *= clo; oacc[nf][1] *= clo;
                oacc[nf][2] *= chi; oacc[nf][3] *= chi;
            }

            // exp -> P (single fp16 fragments)
            u32 pf[4][4];
#pragma unroll
            for (int nf = 0; nf < 8; nf++) {
                float p0 = __expf(sacc[nf][0] - mlo);
                float p1 = __expf(sacc[nf][1] - mlo);
                float p2 = __expf(sacc[nf][2] - mhi);
                float p3 = __expf(sacc[nf][3] - mhi);
                llo += p0 + p1;
                lhi += p2 + p3;
                int kc = nf >> 1, half = nf & 1;
                pf[kc][half * 2 + 0] = pack_f16(p0, p1);
                pf[kc][half * 2 + 1] = pack_f16(p2, p3);
            }

            // O += P V : P(Vh) + P(Vl)
#pragma unroll
            for (int dg = 0; dg < 4; dg++) {
#pragma unroll
                for (int kc = 0; kc < 4; kc++) {
                    u32 off = (u32)((kc * 16 + lr) * AST + dg * 16 + lh * 8) * 2;
                    u32 vh0, vh1, vh2, vh3, vl0, vl1, vl2, vl3;
                    ldsm_x4_t(st + KV_ARRB + off,   vh0, vh1, vh2, vh3);
                    ldsm_x4_t(st + 2*KV_ARRB + off, vl0, vl1, vl2, vl3);
                    float* e = oacc[2 * dg];
                    float* o = oacc[2 * dg + 1];
                    mma_f16(e, pf[kc][0], pf[kc][1], pf[kc][2], pf[kc][3], vh0, vh1);
                    mma_f16(o, pf[kc][0], pf[kc][1], pf[kc][2], pf[kc][3], vh2, vh3);
                    mma_f16(e, pf[kc][0], pf[kc][1], pf[kc][2], pf[kc][3], vl0, vl1);
                    mma_f16(o, pf[kc][0], pf[kc][1], pf[kc][2], pf[kc][3], vl2, vl3);
                }
            }
        }
        __syncthreads();
    }

    llo += __shfl_xor_sync(0xffffffffu, llo, 1);
    llo += __shfl_xor_sync(0xffffffffu, llo, 2);
    lhi += __shfl_xor_sync(0xffffffffu, lhi, 1);
    lhi += __shfl_xor_sync(0xffffffffu, lhi, 2);
    float ilo = 1.f / llo, ihi = 1.f / lhi;

    int b = bh >> 4;
    float* ylo = g_y + ((size_t)b * T_ + rlo) * C_ + h * D_ + cq;
    float* yhi = g_y + ((size_t)b * T_ + rhi) * C_ + h * D_ + cq;
#pragma unroll
    for (int nf = 0; nf < 8; nf++) {
        *(float2*)(ylo + nf * 8) = make_float2(oacc[nf][0] * ilo, oacc[nf][1] * ilo);
        *(float2*)(yhi + nf * 8) = make_float2(oacc[nf][2] * ihi, oacc[nf][3] * ihi);
    }
}

// ---------------------------------------------------------------------------
extern "C" void kernel_launch(void* const* d_in, const int* in_sizes, int n_in,
                              void* d_out, int out_size) {
    const float* x   = (const float*)d_in[0];
    const float* Wq  = (const float*)d_in[1];
    const float* bq  = (const float*)d_in[2];
    const float* Wk  = (const float*)d_in[3];
    const float* bk  = (const float*)d_in[4];
    const float* Wv  = (const float*)d_in[5];
    const float* bv  = (const float*)d_in[6];
    const float* Wp  = (const float*)d_in[7];
    const float* bp  = (const float*)d_in[8];
    const float* tbl = (const float*)d_in[9];
    float* out = (float*)d_out;

    cudaFuncSetAttribute(mma_qkv_kernel,
                         cudaFuncAttributeMaxDynamicSharedMemorySize, SMEM_TOTAL);
    cudaFuncSetAttribute(mma_proj_kernel,
                         cudaFuncAttributeMaxDynamicSharedMemorySize, SMEM_TOTAL);
    cudaFuncSetAttribute(attn_mma_kernel,
                         cudaFuncAttributeMaxDynamicSharedMemorySize, AT_SMEM);

    tables_kernel<<<(T_ * D_ + 255) / 256, 256>>>(tbl);
    split_act_kernel<<<(B_ * T_ * C_ / 4) / 256, 256>>>(x, 0);
    split_w_kernel<<<dim3((C_ * C_ / 4) / 256, 4), 256>>>(Wq, Wk, Wv, Wp);

    mma_qkv_kernel<<<dim3(C_ / 128, (B_ * T_) / 128, 3), 512, SMEM_TOTAL>>>(bq, bk, bv);

    rope_split_kernel<<<(3 * B_ * H_ * T_ * 32) / 256, 256>>>();

    attn_mma_kernel<<<dim3(T_ / 128, B_ * H_), 256, AT_SMEM>>>();

    split_act_kernel<<<(B_ * T_ * C_ / 4) / 256, 256>>>(nullptr, 1);
    mma_proj_kernel<<<dim3(C_ / 128, (B_ * T_) / 128), 512, SMEM_TOTAL>>>(bp, out);
}

// round 9
// speedup vs baseline: 6.8315x; 1.3670x over previous
#include <cuda_runtime.h>
#include <cuda_fp16.h>
#include <math.h>
#include <math_constants.h>

#define B_  2
#define T_  2048
#define C_  1024
#define H_  16
#define D_  64
#define KCH 64               // GEMM K elems per pipeline chunk
#define NCH (C_ / KCH)       // 16 chunks

typedef unsigned int u32;

// ---------------------------------------------------------------------------
// Scratch (__device__ globals: allocation-free rule)
// ---------------------------------------------------------------------------
static __device__ __align__(16) float g_q[(size_t)B_*H_*T_*D_];
static __device__ __align__(16) float g_k[(size_t)B_*H_*T_*D_];
static __device__ __align__(16) float g_v[(size_t)B_*H_*T_*D_];
static __device__ __align__(16) float g_bias[H_*T_];
static __device__ __align__(16) float g_cos[T_*D_];
static __device__ __align__(16) float g_sin[T_*D_];
// fp16 operands (single precision path everywhere)
static __device__ __align__(16) __half g_xf[(size_t)B_*T_*C_];      // x fp16
static __device__ __align__(16) __half g_yf[(size_t)B_*T_*C_];      // attn out fp16
static __device__ __align__(16) __half g_w[4 * (size_t)C_*C_];      // weights fp16
// attention operands (head layout [B,H,T,D])
static __device__ __align__(16) __half g_qf[(size_t)B_*H_*T_*D_];
static __device__ __align__(16) __half g_kf[(size_t)B_*H_*T_*D_];
static __device__ __align__(16) __half g_vf[(size_t)B_*H_*T_*D_];

// ---------------------------------------------------------------------------
// Baseline-PTX helpers (sm_80-compatible: ldmatrix / mma.sync / cp.async)
// ---------------------------------------------------------------------------
__device__ __forceinline__ u32 smem_u32(const void* p) {
    u32 a;
    asm("{ .reg .u64 t; cvta.to.shared.u64 t, %1; cvt.u32.u64 %0, t; }" : "=r"(a) : "l"(p));
    return a;
}
__device__ __forceinline__ void ldsm_x4(u32 addr, u32& r0, u32& r1, u32& r2, u32& r3) {
    asm volatile("ldmatrix.sync.aligned.m8n8.x4.shared.b16 {%0,%1,%2,%3}, [%4];"
                 : "=r"(r0), "=r"(r1), "=r"(r2), "=r"(r3) : "r"(addr));
}
__device__ __forceinline__ void ldsm_x4_t(u32 addr, u32& r0, u32& r1, u32& r2, u32& r3) {
    asm volatile("ldmatrix.sync.aligned.m8n8.x4.trans.shared.b16 {%0,%1,%2,%3}, [%4];"
                 : "=r"(r0), "=r"(r1), "=r"(r2), "=r"(r3) : "r"(addr));
}
__device__ __forceinline__ void mma_f16(float* c, u32 a0, u32 a1, u32 a2, u32 a3,
                                        u32 b0, u32 b1) {
    asm volatile("mma.sync.aligned.m16n8k16.row.col.f32.f16.f16.f32 "
                 "{%0,%1,%2,%3}, {%4,%5,%6,%7}, {%8,%9}, {%0,%1,%2,%3};"
                 : "+f"(c[0]), "+f"(c[1]), "+f"(c[2]), "+f"(c[3])
                 : "r"(a0), "r"(a1), "r"(a2), "r"(a3), "r"(b0), "r"(b1));
}
#define CP_ASYNC16(dst, src) \
    asm volatile("cp.async.cg.shared.global [%0], [%1], 16;" :: "r"(dst), "l"(src))
#define CP_COMMIT() asm volatile("cp.async.commit_group;" ::: "memory")
#define CP_WAIT1()  asm volatile("cp.async.wait_group 1;" ::: "memory")
#define CP_WAIT0()  asm volatile("cp.async.wait_group 0;" ::: "memory")

__device__ __forceinline__ u32 pack_f16(float lo, float hi) {
    __half2 h = __floats2half2_rn(lo, hi);
    return *(u32*)&h;
}

// ---------------------------------------------------------------------------
// Tables
// ---------------------------------------------------------------------------
__global__ void tables_kernel(const float* __restrict__ rel_table) {
    int idx = blockIdx.x * blockDim.x + threadIdx.x;
    if (idx < T_ * D_) {
        int t = idx >> 6;
        int d = idx & 63;
        int j = d & 31;
        float inv = (float)pow(10000.0, -(double)(2 * j) / 64.0);
        float fr = (float)t * inv;
        g_cos[idx] = cosf(fr);
        g_sin[idx] = sinf(fr);
    }
    if (idx < H_ * T_) {
        int h = idx / T_;
        int n = idx % T_;
        int bucket;
        if (n < 16) {
            bucket = n;
        } else {
            float v = logf((float)n * (1.0f / 16.0f)) / 2.0794415416798357f * 16.0f;
            bucket = 16 + (int)v;
            if (bucket > 31) bucket = 31;
        }
        g_bias[idx] = rel_table[bucket * H_ + h];
    }
}

// ---------------------------------------------------------------------------
// fp32 -> fp16 converts
// ---------------------------------------------------------------------------
__global__ void convert_x_kernel(const float* __restrict__ xin) {
    int i = blockIdx.x * 256 + threadIdx.x;
    float4 v = ((const float4*)xin)[i];
    ((__half2*)g_xf)[i * 2 + 0] = __floats2half2_rn(v.x, v.y);
    ((__half2*)g_xf)[i * 2 + 1] = __floats2half2_rn(v.z, v.w);
}

__global__ void convert_w_kernel(const float* __restrict__ Wq, const float* __restrict__ Wk,
                                 const float* __restrict__ Wv, const float* __restrict__ Wp) {
    int z = blockIdx.y;
    const float* W = z == 0 ? Wq : z == 1 ? Wk : z == 2 ? Wv : Wp;
    __half* ow = g_w + (size_t)z * C_ * C_;
    int i = blockIdx.x * 256 + threadIdx.x;
    float4 v = ((const float4*)W)[i];
    ((__half2*)ow)[i * 2 + 0] = __floats2half2_rn(v.x, v.y);
    ((__half2*)ow)[i * 2 + 1] = __floats2half2_rn(v.z, v.w);
}

// ---------------------------------------------------------------------------
// HMMA GEMM v4: A single fp16 x W single fp16 (1 product).
// 128x128 CTA, 512 threads (16 warps 4x4, warp tile 32x32), K chunks of 64.
// mode 0: row-major out; mode 1: head layout [B,H,T,D].
// ---------------------------------------------------------------------------
#define SA 72        // A smem row stride (halves)
#define SB 136       // B smem row stride (halves)
#define A_OFF 0
#define B_OFF (128 * SA * 2)                      // 18432
#define STAGE_BYTES (B_OFF + KCH * SB * 2)        // 35840
#define SMEM_TOTAL (2 * STAGE_BYTES)              // 71680

__device__ __forceinline__ void hmma_gemm_body(
        const __half* __restrict__ Af, const __half* __restrict__ Wf,
        const float* __restrict__ bias, float* __restrict__ out, int mode) {
    extern __shared__ char smem[];
    u32 sb = smem_u32(smem);

    int tid = threadIdx.x;
    int lane = tid & 31;
    int wid = tid >> 5;
    int wm = wid & 3;
    int wn = wid >> 2;
    int bm = blockIdx.y * 128;
    int bn = blockIdx.x * 128;

    float acc[2][4][4];
#pragma unroll
    for (int i = 0; i < 2; i++)
#pragma unroll
        for (int j = 0; j < 4; j++)
#pragma unroll
            for (int r = 0; r < 4; r++) acc[i][j][r] = 0.f;

    auto load_chunk = [&](int c, int s) {
        u32 st = sb + s * STAGE_BYTES;
        int c0 = c * KCH;
#pragma unroll
        for (int u = tid; u < 1024; u += 512) {
            int row = u >> 3, seg = u & 7;
            size_t gofs = (size_t)(bm + row) * C_ + c0 + seg * 8;
            CP_ASYNC16(st + A_OFF + (u32)(row * SA + seg * 8) * 2, Af + gofs);
        }
#pragma unroll
        for (int u = tid; u < 1024; u += 512) {
            int row = u >> 4, seg = u & 15;
            size_t gofs = (size_t)(c0 + row) * C_ + bn + seg * 8;
            CP_ASYNC16(st + B_OFF + (u32)(row * SB + seg * 8) * 2, Wf + gofs);
        }
        CP_COMMIT();
    };

    load_chunk(0, 0);

    int lr = lane & 15;
    int lh = lane >> 4;

    for (int c = 0; c < NCH; c++) {
        int s = c & 1;
        if (c + 1 < NCH) { load_chunk(c + 1, s ^ 1); CP_WAIT1(); }
        else             { CP_WAIT0(); }
        __syncthreads();

        u32 st = sb + s * STAGE_BYTES;
#pragma unroll
        for (int ks = 0; ks < 4; ks++) {
            int k0 = ks * 16;
            u32 af[2][4];
#pragma unroll
            for (int mt = 0; mt < 2; mt++) {
                u32 arow = (u32)(wm * 32 + mt * 16 + lr);
                u32 aoff = (arow * SA + k0 + lh * 8) * 2;
                ldsm_x4(st + A_OFF + aoff, af[mt][0], af[mt][1], af[mt][2], af[mt][3]);
            }
#pragma unroll
            for (int np = 0; np < 2; np++) {
                u32 brow = (u32)(k0 + lr);
                u32 bcol = (u32)(wn * 32 + np * 16 + lh * 8);
                u32 boff = (brow * SB + bcol) * 2;
                u32 b0, b1, b2, b3;
                ldsm_x4_t(st + B_OFF + boff, b0, b1, b2, b3);
#pragma unroll
                for (int mt = 0; mt < 2; mt++) {
                    mma_f16(acc[mt][np * 2],     af[mt][0], af[mt][1], af[mt][2], af[mt][3], b0, b1);
                    mma_f16(acc[mt][np * 2 + 1], af[mt][0], af[mt][1], af[mt][2], af[mt][3], b2, b3);
                }
            }
        }
        __syncthreads();
    }

    int rq = lane >> 2;
    int cq = (lane & 3) * 2;
#pragma unroll
    for (int mt = 0; mt < 2; mt++) {
#pragma unroll
        for (int nt = 0; nt < 4; nt++) {
            int gc = bn + wn * 32 + nt * 8 + cq;
            float b0 = bias[gc], b1 = bias[gc + 1];
#pragma unroll
            for (int half = 0; half < 2; half++) {
                int grow = bm + wm * 32 + mt * 16 + rq + half * 8;
                float2 o;
                o.x = acc[mt][nt][half * 2 + 0] + b0;
                o.y = acc[mt][nt][half * 2 + 1] + b1;
                float* op;
                if (mode == 0) {
                    op = out + (size_t)grow * C_ + gc;
                } else {
                    int h = gc >> 6, d0 = gc & 63;
                    int b = grow >> 11, t = grow & (T_ - 1);
                    op = out + (((size_t)b * H_ + h) * T_ + t) * D_ + d0;
                }
                *(float2*)op = o;
            }
        }
    }
}

__global__ __launch_bounds__(512, 1) void mma_qkv_kernel(
        const float* __restrict__ bq, const float* __restrict__ bk,
        const float* __restrict__ bv) {
    int z = blockIdx.z;
    const __half* Wf = g_w + (size_t)z * C_ * C_;
    const float* bias = z == 0 ? bq : z == 1 ? bk : bv;
    float* dst = z == 0 ? g_q : z == 1 ? g_k : g_v;
    hmma_gemm_body(g_xf, Wf, bias, dst, 1);
}

__global__ __launch_bounds__(512, 1) void mma_proj_kernel(
        const float* __restrict__ bp, float* __restrict__ out) {
    hmma_gemm_body(g_yf, g_w + 3 * (size_t)C_ * C_, bp, out, 0);
}

// ---------------------------------------------------------------------------
// Rope + fp16 convert. seg 0: q (rotate + 1/8), 1: k (rotate), 2: v
// ---------------------------------------------------------------------------
__global__ void rope_split_kernel() {
    const int NH = B_ * H_ * T_ * 32;
    int idx = blockIdx.x * 256 + threadIdx.x;
    int seg = idx / NH;
    int r = idx - seg * NH;
    int d = r & 31;
    int row = r >> 5;
    int t = row & (T_ - 1);
    size_t p = ((size_t)row << 6) + d;

    if (seg == 0) {
        float c = g_cos[(t << 6) + d], s = g_sin[(t << 6) + d];
        float x1 = g_q[p], x2 = g_q[p + 32];
        g_qf[p]      = __float2half_rn((x1 * c - x2 * s) * 0.125f);
        g_qf[p + 32] = __float2half_rn((x2 * c + x1 * s) * 0.125f);
    } else if (seg == 1) {
        float c = g_cos[(t << 6) + d], s = g_sin[(t << 6) + d];
        float x1 = g_k[p], x2 = g_k[p + 32];
        g_kf[p]      = __float2half_rn(x1 * c - x2 * s);
        g_kf[p + 32] = __float2half_rn(x2 * c + x1 * s);
    } else {
        g_vf[p]      = __float2half_rn(g_v[p]);
        g_vf[p + 32] = __float2half_rn(g_v[p + 32]);
    }
}

// ---------------------------------------------------------------------------
// HMMA flash attention v3: QK 1-product, PV 1-product, fp16 output direct.
// CTA: 128 queries x one (b,h), 8 warps x 16 rows, key blocks of 64.
// ---------------------------------------------------------------------------
#define AST 72
#define KV_ARRB (64 * AST * 2)               // 9216
#define KV_STAGEB (2 * KV_ARRB)              // 18432 (K, V)
#define AT_SMEM (2 * KV_STAGEB + T_ * 4)     // 45056

__global__ __launch_bounds__(256, 1) void attn_mma_kernel() {
    extern __shared__ char asm_[];
    u32 sbase = smem_u32(asm_);
    float* sbias = (float*)(asm_ + 2 * KV_STAGEB);
    __half* sst = (__half*)asm_;

    int bh = blockIdx.y;
    int h = bh & (H_ - 1);
    int qb = gridDim.x - 1 - blockIdx.x;
    int q0 = qb * 128;
    int tid = threadIdx.x;
    int lane = tid & 31;
    int w = tid >> 5;
    int qw = q0 + w * 16;

    const __half* qf = g_qf + ((size_t)bh * T_ + q0) * D_;
    size_t kvo = (size_t)bh * T_ * D_;

    {
        const float4* b4 = (const float4*)(g_bias + h * T_);
        for (int i = tid; i < T_ / 4; i += 256) {
            float4 v = b4[i];
            v.x *= 0.125f; v.y *= 0.125f; v.z *= 0.125f; v.w *= 0.125f;
            ((float4*)sbias)[i] = v;
        }
    }
    // stage Q (128x64 fp16) into stage-0 area
    for (int u = tid; u < 1024; u += 256) {
        int row = u >> 3, seg = u & 7;
        *(uint4*)(sst + row * AST + seg * 8) =
            *(const uint4*)(qf + row * 64 + seg * 8);
    }
    __syncthreads();

    u32 qfr[4][4];
    {
        int lr = lane & 15, lh = lane >> 4;
#pragma unroll
        for (int kc = 0; kc < 4; kc++) {
            u32 off = (u32)((w * 16 + lr) * AST + kc * 16 + lh * 8) * 2;
            ldsm_x4(sbase + off, qfr[kc][0], qfr[kc][1], qfr[kc][2], qfr[kc][3]);
        }
    }
    __syncthreads();

    auto load_kv = [&](int blk, int s) {
        u32 st = sbase + s * KV_STAGEB;
        const __half* kf = g_kf + kvo + (size_t)blk * 64 * 64;
        const __half* vf = g_vf + kvo + (size_t)blk * 64 * 64;
#pragma unroll
        for (int u = tid; u < 512; u += 256) {
            int row = u >> 3, seg = u & 7;
            u32 doff = (u32)(row * AST + seg * 8) * 2;
            int goff = row * 64 + seg * 8;
            CP_ASYNC16(st + doff,           kf + goff);
            CP_ASYNC16(st + KV_ARRB + doff, vf + goff);
        }
        CP_COMMIT();
    };

    int nblk = q0 / 64 + 2;
    load_kv(0, 0);

    float mlo = -CUDART_INF_F, mhi = -CUDART_INF_F;
    float llo = 0.f, lhi = 0.f;
    float oacc[8][4];
#pragma unroll
    for (int i = 0; i < 8; i++)
#pragma unroll
        for (int j = 0; j < 4; j++) oacc[i][j] = 0.f;

    int rlo = qw + (lane >> 2);
    int rhi = rlo + 8;
    int cq = (lane & 3) * 2;

    for (int blk = 0; blk < nblk; blk++) {
        int s = blk & 1;
        if (blk + 1 < nblk) { load_kv(blk + 1, s ^ 1); CP_WAIT1(); }
        else                { CP_WAIT0(); }
        __syncthreads();

        int j0 = blk * 64;
        if (j0 <= qw + 15) {
            u32 st = sbase + s * KV_STAGEB;
            int lr = lane & 15, lh = lane >> 4;

            // S = Q K^T (1 product)
            float sacc[8][4];
#pragma unroll
            for (int i = 0; i < 8; i++)
#pragma unroll
                for (int j = 0; j < 4; j++) sacc[i][j] = 0.f;
#pragma unroll
            for (int kg = 0; kg < 4; kg++) {
#pragma unroll
                for (int kc = 0; kc < 4; kc++) {
                    u32 off = (u32)((kg * 16 + lr) * AST + kc * 16 + lh * 8) * 2;
                    u32 k0, k1, k2, k3;
                    ldsm_x4(st + off, k0, k1, k2, k3);
                    mma_f16(sacc[2 * kg],     qfr[kc][0], qfr[kc][1], qfr[kc][2], qfr[kc][3], k0, k2);
                    mma_f16(sacc[2 * kg + 1], qfr[kc][0], qfr[kc][1], qfr[kc][2], qfr[kc][3], k1, k3);
                }
            }

            // bias + causal mask
#pragma unroll
            for (int nf = 0; nf < 8; nf++) {
                int jc = j0 + nf * 8 + cq;
                int d0 = rlo - jc;
                int d2 = rhi - jc;
                sacc[nf][0] = (d0 >= 0) ? sacc[nf][0] + sbias[d0]     : -CUDART_INF_F;
                sacc[nf][1] = (d0 >= 1) ? sacc[nf][1] + sbias[d0 - 1] : -CUDART_INF_F;
                sacc[nf][2] = (d2 >= 0) ? sacc[nf][2] + sbias[d2]     : -CUDART_INF_F;
                sacc[nf][3] = (d2 >= 1) ? sacc[nf][3] + sbias[d2 - 1] : -CUDART_INF_F;
            }

            // row max
            float bmlo = sacc[0][0], bmhi = sacc[0][2];
#pragma unroll
            for (int nf = 0; nf < 8; nf++) {
                bmlo = fmaxf(bmlo, fmaxf(sacc[nf][0], sacc[nf][1]));
                bmhi = fmaxf(bmhi, fmaxf(sacc[nf][2], sacc[nf][3]));
            }
            bmlo = fmaxf(bmlo, __shfl_xor_sync(0xffffffffu, bmlo, 1));
            bmlo = fmaxf(bmlo, __shfl_xor_sync(0xffffffffu, bmlo, 2));
            bmhi = fmaxf(bmhi, __shfl_xor_sync(0xffffffffu, bmhi, 1));
            bmhi = fmaxf(bmhi, __shfl_xor_sync(0xffffffffu, bmhi, 2));

            float nmlo = fmaxf(mlo, bmlo), nmhi = fmaxf(mhi, bmhi);
            float clo = __expf(mlo - nmlo), chi = __expf(mhi - nmhi);
            mlo = nmlo; mhi = nmhi;
            llo *= clo; lhi *= chi;
#pragma unroll
            for (int nf = 0; nf < 8; nf++) {
                oacc[nf][0] *= clo; oacc[nf][1] *= clo;
                oacc[nf][2] *= chi; oacc[nf][3] *= chi;
            }

            // exp -> P (fp16 fragments)
            u32 pf[4][4];
#pragma unroll
            for (int nf = 0; nf < 8; nf++) {
                float p0 = __expf(sacc[nf][0] - mlo);
                float p1 = __expf(sacc[nf][1] - mlo);
                float p2 = __expf(sacc[nf][2] - mhi);
                float p3 = __expf(sacc[nf][3] - mhi);
                llo += p0 + p1;
                lhi += p2 + p3;
                int kc = nf >> 1, half = nf & 1;
                pf[kc][half * 2 + 0] = pack_f16(p0, p1);
                pf[kc][half * 2 + 1] = pack_f16(p2, p3);
            }

            // O += P V (1 product)
#pragma unroll
            for (int dg = 0; dg < 4; dg++) {
#pragma unroll
                for (int kc = 0; kc < 4; kc++) {
                    u32 off = (u32)((kc * 16 + lr) * AST + dg * 16 + lh * 8) * 2;
                    u32 v0, v1, v2, v3;
                    ldsm_x4_t(st + KV_ARRB + off, v0, v1, v2, v3);
                    mma_f16(oacc[2 * dg],     pf[kc][0], pf[kc][1], pf[kc][2], pf[kc][3], v0, v1);
                    mma_f16(oacc[2 * dg + 1], pf[kc][0], pf[kc][1], pf[kc][2], pf[kc][3], v2, v3);
                }
            }
        }
        __syncthreads();
    }

    llo += __shfl_xor_sync(0xffffffffu, llo, 1);
    llo += __shfl_xor_sync(0xffffffffu, llo, 2);
    lhi += __shfl_xor_sync(0xffffffffu, lhi, 1);
    lhi += __shfl_xor_sync(0xffffffffu, lhi, 2);
    float ilo = 1.f / llo, ihi = 1.f / lhi;

    // write fp16 directly to proj input g_yf [B*T, C]
    int b = bh >> 4;
    __half* ylo = g_yf + ((size_t)b * T_ + rlo) * C_ + h * D_ + cq;
    __half* yhi = g_yf + ((size_t)b * T_ + rhi) * C_ + h * D_ + cq;
#pragma unroll
    for (int nf = 0; nf < 8; nf++) {
        *(__half2*)(ylo + nf * 8) = __floats2half2_rn(oacc[nf][0] * ilo, oacc[nf][1] * ilo);
        *(__half2*)(yhi + nf * 8) = __floats2half2_rn(oacc[nf][2] * ihi, oacc[nf][3] * ihi);
    }
}

// ---------------------------------------------------------------------------
extern "C" void kernel_launch(void* const* d_in, const int* in_sizes, int n_in,
                              void* d_out, int out_size) {
    const float* x   = (const float*)d_in[0];
    const float* Wq  = (const float*)d_in[1];
    const float* bq  = (const float*)d_in[2];
    const float* Wk  = (const float*)d_in[3];
    const float* bk  = (const float*)d_in[4];
    const float* Wv  = (const float*)d_in[5];
    const float* bv  = (const float*)d_in[6];
    const float* Wp  = (const float*)d_in[7];
    const float* bp  = (const float*)d_in[8];
    const float* tbl = (const float*)d_in[9];
    float* out = (float*)d_out;

    cudaFuncSetAttribute(mma_qkv_kernel,
                         cudaFuncAttributeMaxDynamicSharedMemorySize, SMEM_TOTAL);
    cudaFuncSetAttribute(mma_proj_kernel,
                         cudaFuncAttributeMaxDynamicSharedMemorySize, SMEM_TOTAL);
    cudaFuncSetAttribute(attn_mma_kernel,
                         cudaFuncAttributeMaxDynamicSharedMemorySize, AT_SMEM);

    tables_kernel<<<(T_ * D_ + 255) / 256, 256>>>(tbl);
    convert_x_kernel<<<(B_ * T_ * C_ / 4) / 256, 256>>>(x);
    convert_w_kernel<<<dim3((C_ * C_ / 4) / 256, 4), 256>>>(Wq, Wk, Wv, Wp);

    mma_qkv_kernel<<<dim3(C_ / 128, (B_ * T_) / 128, 3), 512, SMEM_TOTAL>>>(bq, bk, bv);

    rope_split_kernel<<<(3 * B_ * H_ * T_ * 32) / 256, 256>>>();

    attn_mma_kernel<<<dim3(T_ / 128, B_ * H_), 256, AT_SMEM>>>();

    mma_proj_kernel<<<dim3(C_ / 128, (B_ * T_) / 128), 512, SMEM_TOTAL>>>(bp, out);
}

// round 10
// speedup vs baseline: 7.2566x; 1.0622x over previous
#include <cuda_runtime.h>
#include <cuda_fp16.h>
#include <math.h>
#include <math_constants.h>

#define B_  2
#define T_  2048
#define C_  1024
#define H_  16
#define D_  64
#define KCH 64               // GEMM K elems per pipeline chunk
#define NCH (C_ / KCH)       // 16 chunks

typedef unsigned int u32;

// ---------------------------------------------------------------------------
// Scratch (__device__ globals: allocation-free rule)
// ---------------------------------------------------------------------------
static __device__ __align__(16) float g_bias[H_*T_];
static __device__ __align__(16) float g_cos[T_*D_];
static __device__ __align__(16) float g_sin[T_*D_];
// fp16 operands
static __device__ __align__(16) __half g_xf[(size_t)B_*T_*C_];      // x fp16
static __device__ __align__(16) __half g_yf[(size_t)B_*T_*C_];      // attn out fp16
static __device__ __align__(16) __half g_w[4 * (size_t)C_*C_];      // weights fp16
// attention operands (head layout [B,H,T,D]), written by fused qkv epilogue
static __device__ __align__(16) __half g_qf[(size_t)B_*H_*T_*D_];
static __device__ __align__(16) __half g_kf[(size_t)B_*H_*T_*D_];
static __device__ __align__(16) __half g_vf[(size_t)B_*H_*T_*D_];

// ---------------------------------------------------------------------------
// Baseline-PTX helpers (sm_80-compatible: ldmatrix / mma.sync / cp.async)
// ---------------------------------------------------------------------------
__device__ __forceinline__ u32 smem_u32(const void* p) {
    u32 a;
    asm("{ .reg .u64 t; cvta.to.shared.u64 t, %1; cvt.u32.u64 %0, t; }" : "=r"(a) : "l"(p));
    return a;
}
__device__ __forceinline__ void ldsm_x4(u32 addr, u32& r0, u32& r1, u32& r2, u32& r3) {
    asm volatile("ldmatrix.sync.aligned.m8n8.x4.shared.b16 {%0,%1,%2,%3}, [%4];"
                 : "=r"(r0), "=r"(r1), "=r"(r2), "=r"(r3) : "r"(addr));
}
__device__ __forceinline__ void ldsm_x4_t(u32 addr, u32& r0, u32& r1, u32& r2, u32& r3) {
    asm volatile("ldmatrix.sync.aligned.m8n8.x4.trans.shared.b16 {%0,%1,%2,%3}, [%4];"
                 : "=r"(r0), "=r"(r1), "=r"(r2), "=r"(r3) : "r"(addr));
}
__device__ __forceinline__ void mma_f16(float* c, u32 a0, u32 a1, u32 a2, u32 a3,
                                        u32 b0, u32 b1) {
    asm volatile("mma.sync.aligned.m16n8k16.row.col.f32.f16.f16.f32 "
                 "{%0,%1,%2,%3}, {%4,%5,%6,%7}, {%8,%9}, {%0,%1,%2,%3};"
                 : "+f"(c[0]), "+f"(c[1]), "+f"(c[2]), "+f"(c[3])
                 : "r"(a0), "r"(a1), "r"(a2), "r"(a3), "r"(b0), "r"(b1));
}
#define CP_ASYNC16(dst, src) \
    asm volatile("cp.async.cg.shared.global [%0], [%1], 16;" :: "r"(dst), "l"(src))
#define CP_COMMIT() asm volatile("cp.async.commit_group;" ::: "memory")
#define CP_WAIT1()  asm volatile("cp.async.wait_group 1;" ::: "memory")
#define CP_WAIT0()  asm volatile("cp.async.wait_group 0;" ::: "memory")

__device__ __forceinline__ u32 pack_f16(float lo, float hi) {
    __half2 h = __floats2half2_rn(lo, hi);
    return *(u32*)&h;
}

// ---------------------------------------------------------------------------
// Tables
// ---------------------------------------------------------------------------
__global__ void tables_kernel(const float* __restrict__ rel_table) {
    int idx = blockIdx.x * blockDim.x + threadIdx.x;
    if (idx < T_ * D_) {
        int t = idx >> 6;
        int d = idx & 63;
        int j = d & 31;
        float inv = (float)pow(10000.0, -(double)(2 * j) / 64.0);
        float fr = (float)t * inv;
        g_cos[idx] = cosf(fr);
        g_sin[idx] = sinf(fr);
    }
    if (idx < H_ * T_) {
        int h = idx / T_;
        int n = idx % T_;
        int bucket;
        if (n < 16) {
            bucket = n;
        } else {
            float v = logf((float)n * (1.0f / 16.0f)) / 2.0794415416798357f * 16.0f;
            bucket = 16 + (int)v;
            if (bucket > 31) bucket = 31;
        }
        g_bias[idx] = rel_table[bucket * H_ + h];
    }
}

// ---------------------------------------------------------------------------
// fp32 -> fp16 converts
// ---------------------------------------------------------------------------
__global__ void convert_x_kernel(const float* __restrict__ xin) {
    int i = blockIdx.x * 256 + threadIdx.x;
    float4 v = ((const float4*)xin)[i];
    ((__half2*)g_xf)[i * 2 + 0] = __floats2half2_rn(v.x, v.y);
    ((__half2*)g_xf)[i * 2 + 1] = __floats2half2_rn(v.z, v.w);
}

__global__ void convert_w_kernel(const float* __restrict__ Wq, const float* __restrict__ Wk,
                                 const float* __restrict__ Wv, const float* __restrict__ Wp) {
    int z = blockIdx.y;
    const float* W = z == 0 ? Wq : z == 1 ? Wk : z == 2 ? Wv : Wp;
    __half* ow = g_w + (size_t)z * C_ * C_;
    int i = blockIdx.x * 256 + threadIdx.x;
    float4 v = ((const float4*)W)[i];
    ((__half2*)ow)[i * 2 + 0] = __floats2half2_rn(v.x, v.y);
    ((__half2*)ow)[i * 2 + 1] = __floats2half2_rn(v.z, v.w);
}

// ---------------------------------------------------------------------------
// HMMA GEMM v5: A fp16 x W fp16, fused epilogues.
// 128x128 CTA, 512 threads (16 warps 4x4, warp tile 32x32), K chunks of 64.
// mode 0: proj (fp32 row-major out)
// mode 1: Q (rope + 1/8 scale -> g_qf fp16 head layout, via smem staging)
// mode 2: K (rope -> g_kf)
// mode 3: V (direct fp16 -> g_vf)
// ---------------------------------------------------------------------------
#define SA 72        // A smem row stride (halves)
#define SB 136       // B smem row stride (halves)
#define A_OFF 0
#define B_OFF (128 * SA * 2)                      // 18432
#define STAGE_BYTES (B_OFF + KCH * SB * 2)        // 35840
#define SMEM_TOTAL (2 * STAGE_BYTES)              // 71680  (>= 128*132*4 staging)

__device__ __forceinline__ void hmma_gemm_body(
        const __half* __restrict__ Af, const __half* __restrict__ Wf,
        const float* __restrict__ bias, void* outp, int mode) {
    extern __shared__ char smem[];
    u32 sb = smem_u32(smem);

    int tid = threadIdx.x;
    int lane = tid & 31;
    int wid = tid >> 5;
    int wm = wid & 3;
    int wn = wid >> 2;
    int bm = blockIdx.y * 128;
    int bn = blockIdx.x * 128;

    float acc[2][4][4];
#pragma unroll
    for (int i = 0; i < 2; i++)
#pragma unroll
        for (int j = 0; j < 4; j++)
#pragma unroll
            for (int r = 0; r < 4; r++) acc[i][j][r] = 0.f;

    auto load_chunk = [&](int c, int s) {
        u32 st = sb + s * STAGE_BYTES;
        int c0 = c * KCH;
#pragma unroll
        for (int u = tid; u < 1024; u += 512) {
            int row = u >> 3, seg = u & 7;
            size_t gofs = (size_t)(bm + row) * C_ + c0 + seg * 8;
            CP_ASYNC16(st + A_OFF + (u32)(row * SA + seg * 8) * 2, Af + gofs);
        }
#pragma unroll
        for (int u = tid; u < 1024; u += 512) {
            int row = u >> 4, seg = u & 15;
            size_t gofs = (size_t)(c0 + row) * C_ + bn + seg * 8;
            CP_ASYNC16(st + B_OFF + (u32)(row * SB + seg * 8) * 2, Wf + gofs);
        }
        CP_COMMIT();
    };

    load_chunk(0, 0);

    int lr = lane & 15;
    int lh = lane >> 4;

    for (int c = 0; c < NCH; c++) {
        int s = c & 1;
        if (c + 1 < NCH) { load_chunk(c + 1, s ^ 1); CP_WAIT1(); }
        else             { CP_WAIT0(); }
        __syncthreads();

        u32 st = sb + s * STAGE_BYTES;
#pragma unroll
        for (int ks = 0; ks < 4; ks++) {
            int k0 = ks * 16;
            u32 af[2][4];
#pragma unroll
            for (int mt = 0; mt < 2; mt++) {
                u32 arow = (u32)(wm * 32 + mt * 16 + lr);
                u32 aoff = (arow * SA + k0 + lh * 8) * 2;
                ldsm_x4(st + A_OFF + aoff, af[mt][0], af[mt][1], af[mt][2], af[mt][3]);
            }
#pragma unroll
            for (int np = 0; np < 2; np++) {
                u32 brow = (u32)(k0 + lr);
                u32 bcol = (u32)(wn * 32 + np * 16 + lh * 8);
                u32 boff = (brow * SB + bcol) * 2;
                u32 b0, b1, b2, b3;
                ldsm_x4_t(st + B_OFF + boff, b0, b1, b2, b3);
#pragma unroll
                for (int mt = 0; mt < 2; mt++) {
                    mma_f16(acc[mt][np * 2],     af[mt][0], af[mt][1], af[mt][2], af[mt][3], b0, b1);
                    mma_f16(acc[mt][np * 2 + 1], af[mt][0], af[mt][1], af[mt][2], af[mt][3], b2, b3);
                }
            }
        }
        __syncthreads();
    }

    int rq = lane >> 2;
    int cq = (lane & 3) * 2;

    if (mode == 0) {
        float* out = (float*)outp;
#pragma unroll
        for (int mt = 0; mt < 2; mt++)
#pragma unroll
            for (int nt = 0; nt < 4; nt++) {
                int gc = bn + wn * 32 + nt * 8 + cq;
                float b0 = bias[gc], b1 = bias[gc + 1];
#pragma unroll
                for (int half = 0; half < 2; half++) {
                    int grow = bm + wm * 32 + mt * 16 + rq + half * 8;
                    float2 o;
                    o.x = acc[mt][nt][half * 2 + 0] + b0;
                    o.y = acc[mt][nt][half * 2 + 1] + b1;
                    *(float2*)(out + (size_t)grow * C_ + gc) = o;
                }
            }
    } else if (mode == 3) {
        __half* out = (__half*)outp;
#pragma unroll
        for (int mt = 0; mt < 2; mt++)
#pragma unroll
            for (int nt = 0; nt < 4; nt++) {
                int gc = bn + wn * 32 + nt * 8 + cq;
                float b0 = bias[gc], b1 = bias[gc + 1];
                int h = gc >> 6, d0 = gc & 63;
#pragma unroll
                for (int half = 0; half < 2; half++) {
                    int grow = bm + wm * 32 + mt * 16 + rq + half * 8;
                    int b = grow >> 11, t = grow & (T_ - 1);
                    __half2 o = __floats2half2_rn(acc[mt][nt][half * 2 + 0] + b0,
                                                  acc[mt][nt][half * 2 + 1] + b1);
                    *(__half2*)(out + (((size_t)b * H_ + h) * T_ + t) * D_ + d0) = o;
                }
            }
    } else {
        // Q/K: stage fp32 tile in smem, then rope pairs (d, d+32) -> fp16
        float* cs = (float*)smem;
#pragma unroll
        for (int mt = 0; mt < 2; mt++)
#pragma unroll
            for (int nt = 0; nt < 4; nt++) {
                int lc = wn * 32 + nt * 8 + cq;
                int gc = bn + lc;
                float b0 = bias[gc], b1 = bias[gc + 1];
#pragma unroll
                for (int half = 0; half < 2; half++) {
                    int lrow = wm * 32 + mt * 16 + rq + half * 8;
                    cs[lrow * 132 + lc]     = acc[mt][nt][half * 2 + 0] + b0;
                    cs[lrow * 132 + lc + 1] = acc[mt][nt][half * 2 + 1] + b1;
                }
            }
        __syncthreads();

        __half* out = (__half*)outp;
        float qscale = (mode == 1) ? 0.125f : 1.0f;
#pragma unroll
        for (int u = tid; u < 8192; u += 512) {
            int r  = u >> 6;
            int pp = u & 63;
            int c  = (pp & 31) + ((pp >> 5) << 6);   // 0..31, 64..95
            int gc = bn + c;
            int h = gc >> 6, d = gc & 63;            // d in [0,32)
            int grow = bm + r;
            int b = grow >> 11, t = grow & (T_ - 1);
            float x1 = cs[r * 132 + c];
            float x2 = cs[r * 132 + c + 32];
            float co = g_cos[(t << 6) + d];
            float si = g_sin[(t << 6) + d];
            float y1 = (x1 * co - x2 * si) * qscale;
            float y2 = (x2 * co + x1 * si) * qscale;
            __half* dp = out + (((size_t)b * H_ + h) * T_ + t) * D_ + d;
            dp[0]  = __float2half_rn(y1);
            dp[32] = __float2half_rn(y2);
        }
    }
}

__global__ __launch_bounds__(512, 1) void mma_qkv_kernel(
        const float* __restrict__ bq, const float* __restrict__ bk,
        const float* __restrict__ bv) {
    int z = blockIdx.z;
    const __half* Wf = g_w + (size_t)z * C_ * C_;
    const float* bias = z == 0 ? bq : z == 1 ? bk : bv;
    void* dst = z == 0 ? (void*)g_qf : z == 1 ? (void*)g_kf : (void*)g_vf;
    hmma_gemm_body(g_xf, Wf, bias, dst, z + 1);
}

__global__ __launch_bounds__(512, 1) void mma_proj_kernel(
        const float* __restrict__ bp, float* __restrict__ out) {
    hmma_gemm_body(g_yf, g_w + 3 * (size_t)C_ * C_, bp, out, 0);
}

// ---------------------------------------------------------------------------
// HMMA flash attention v4: 64 queries / CTA (4 warps), QK 1-product,
// PV 1-product, fp16 output direct to g_yf.
// ---------------------------------------------------------------------------
#define AST 72
#define KV_ARRB (64 * AST * 2)               // 9216
#define KV_STAGEB (2 * KV_ARRB)              // 18432 (K, V)
#define AT_SMEM (2 * KV_STAGEB + T_ * 4)     // 45056

__global__ __launch_bounds__(128) void attn_mma_kernel() {
    extern __shared__ char asm_[];
    u32 sbase = smem_u32(asm_);
    float* sbias = (float*)(asm_ + 2 * KV_STAGEB);
    __half* sst = (__half*)asm_;

    int bh = blockIdx.y;
    int h = bh & (H_ - 1);
    int qb = gridDim.x - 1 - blockIdx.x;      // big-work CTAs first
    int q0 = qb * 64;
    int tid = threadIdx.x;
    int lane = tid & 31;
    int w = tid >> 5;                         // 0..3
    int qw = q0 + w * 16;

    const __half* qf = g_qf + ((size_t)bh * T_ + q0) * D_;
    size_t kvo = (size_t)bh * T_ * D_;

    {
        const float4* b4 = (const float4*)(g_bias + h * T_);
        for (int i = tid; i < T_ / 4; i += 128) {
            float4 v = b4[i];
            v.x *= 0.125f; v.y *= 0.125f; v.z *= 0.125f; v.w *= 0.125f;
            ((float4*)sbias)[i] = v;
        }
    }
    // stage Q (64x64 fp16) into stage-0 area
    for (int u = tid; u < 512; u += 128) {
        int row = u >> 3, seg = u & 7;
        *(uint4*)(sst + row * AST + seg * 8) =
            *(const uint4*)(qf + row * 64 + seg * 8);
    }
    __syncthreads();

    u32 qfr[4][4];
    {
        int lr = lane & 15, lh = lane >> 4;
#pragma unroll
        for (int kc = 0; kc < 4; kc++) {
            u32 off = (u32)((w * 16 + lr) * AST + kc * 16 + lh * 8) * 2;
            ldsm_x4(sbase + off, qfr[kc][0], qfr[kc][1], qfr[kc][2], qfr[kc][3]);
        }
    }
    __syncthreads();

    auto load_kv = [&](int blk, int s) {
        u32 st = sbase + s * KV_STAGEB;
        const __half* kf = g_kf + kvo + (size_t)blk * 64 * 64;
        const __half* vf = g_vf + kvo + (size_t)blk * 64 * 64;
#pragma unroll
        for (int u = tid; u < 512; u += 128) {
            int row = u >> 3, seg = u & 7;
            u32 doff = (u32)(row * AST + seg * 8) * 2;
            int goff = row * 64 + seg * 8;
            CP_ASYNC16(st + doff,           kf + goff);
            CP_ASYNC16(st + KV_ARRB + doff, vf + goff);
        }
        CP_COMMIT();
    };

    int nblk = qb + 1;
    load_kv(0, 0);

    float mlo = -CUDART_INF_F, mhi = -CUDART_INF_F;
    float llo = 0.f, lhi = 0.f;
    float oacc[8][4];
#pragma unroll
    for (int i = 0; i < 8; i++)
#pragma unroll
        for (int j = 0; j < 4; j++) oacc[i][j] = 0.f;

    int rlo = qw + (lane >> 2);
    int rhi = rlo + 8;
    int cq = (lane & 3) * 2;

    for (int blk = 0; blk < nblk; blk++) {
        int s = blk & 1;
        if (blk + 1 < nblk) { load_kv(blk + 1, s ^ 1); CP_WAIT1(); }
        else                { CP_WAIT0(); }
        __syncthreads();

        int j0 = blk * 64;
        {
            u32 st = sbase + s * KV_STAGEB;
            int lr = lane & 15, lh = lane >> 4;

            // S = Q K^T
            float sacc[8][4];
#pragma unroll
            for (int i = 0; i < 8; i++)
#pragma unroll
                for (int j = 0; j < 4; j++) sacc[i][j] = 0.f;
#pragma unroll
            for (int kg = 0; kg < 4; kg++) {
#pragma unroll
                for (int kc = 0; kc < 4; kc++) {
                    u32 off = (u32)((kg * 16 + lr) * AST + kc * 16 + lh * 8) * 2;
                    u32 k0, k1, k2, k3;
                    ldsm_x4(st + off, k0, k1, k2, k3);
                    mma_f16(sacc[2 * kg],     qfr[kc][0], qfr[kc][1], qfr[kc][2], qfr[kc][3], k0, k2);
                    mma_f16(sacc[2 * kg + 1], qfr[kc][0], qfr[kc][1], qfr[kc][2], qfr[kc][3], k1, k3);
                }
            }

            // bias + causal mask
#pragma unroll
            for (int nf = 0; nf < 8; nf++) {
                int jc = j0 + nf * 8 + cq;
                int d0 = rlo - jc;
                int d2 = rhi - jc;
                sacc[nf][0] = (d0 >= 0) ? sacc[nf][0] + sbias[d0]     : -CUDART_INF_F;
                sacc[nf][1] = (d0 >= 1) ? sacc[nf][1] + sbias[d0 - 1] : -CUDART_INF_F;
                sacc[nf][2] = (d2 >= 0) ? sacc[nf][2] + sbias[d2]     : -CUDART_INF_F;
                sacc[nf][3] = (d2 >= 1) ? sacc[nf][3] + sbias[d2 - 1] : -CUDART_INF_F;
            }

            // row max
            float bmlo = sacc[0][0], bmhi = sacc[0][2];
#pragma unroll
            for (int nf = 0; nf < 8; nf++) {
                bmlo = fmaxf(bmlo, fmaxf(sacc[nf][0], sacc[nf][1]));
                bmhi = fmaxf(bmhi, fmaxf(sacc[nf][2], sacc[nf][3]));
            }
            bmlo = fmaxf(bmlo, __shfl_xor_sync(0xffffffffu, bmlo, 1));
            bmlo = fmaxf(bmlo, __shfl_xor_sync(0xffffffffu, bmlo, 2));
            bmhi = fmaxf(bmhi, __shfl_xor_sync(0xffffffffu, bmhi, 1));
            bmhi = fmaxf(bmhi, __shfl_xor_sync(0xffffffffu, bmhi, 2));

            float nmlo = fmaxf(mlo, bmlo), nmhi = fmaxf(mhi, bmhi);
            float clo = __expf(mlo - nmlo), chi = __expf(mhi - nmhi);
            mlo = nmlo; mhi = nmhi;
            llo *= clo; lhi *= chi;
#pragma unroll
            for (int nf = 0; nf < 8; nf++) {
                oacc[nf][0] *= clo; oacc[nf][1] *= clo;
                oacc[nf][2] *= chi; oacc[nf][3] *= chi;
            }

            // exp -> P (fp16 fragments)
            u32 pf[4][4];
#pragma unroll
            for (int nf = 0; nf < 8; nf++) {
                float p0 = __expf(sacc[nf][0] - mlo);
                float p1 = __expf(sacc[nf][1] - mlo);
                float p2 = __expf(sacc[nf][2] - mhi);
                float p3 = __expf(sacc[nf][3] - mhi);
                llo += p0 + p1;
                lhi += p2 + p3;
                int kc = nf >> 1, half = nf & 1;
                pf[kc][half * 2 + 0] = pack_f16(p0, p1);
                pf[kc][half * 2 + 1] = pack_f16(p2, p3);
            }

            // O += P V
#pragma unroll
            for (int dg = 0; dg < 4; dg++) {
#pragma unroll
                for (int kc = 0; kc < 4; kc++) {
                    u32 off = (u32)((kc * 16 + lr) * AST + dg * 16 + lh * 8) * 2;
                    u32 v0, v1, v2, v3;
                    ldsm_x4_t(st + KV_ARRB + off, v0, v1, v2, v3);
                    mma_f16(oacc[2 * dg],     pf[kc][0], pf[kc][1], pf[kc][2], pf[kc][3], v0, v1);
                    mma_f16(oacc[2 * dg + 1], pf[kc][0], pf[kc][1], pf[kc][2], pf[kc][3], v2, v3);
                }
            }
        }
        __syncthreads();
    }

    llo += __shfl_xor_sync(0xffffffffu, llo, 1);
    llo += __shfl_xor_sync(0xffffffffu, llo, 2);
    lhi += __shfl_xor_sync(0xffffffffu, lhi, 1);
    lhi += __shfl_xor_sync(0xffffffffu, lhi, 2);
    float ilo = 1.f / llo, ihi = 1.f / lhi;

    // write fp16 directly to proj input g_yf [B*T, C]
    int b = bh >> 4;
    __half* ylo = g_yf + ((size_t)b * T_ + rlo) * C_ + h * D_ + cq;
    __half* yhi = g_yf + ((size_t)b * T_ + rhi) * C_ + h * D_ + cq;
#pragma unroll
    for (int nf = 0; nf < 8; nf++) {
        *(__half2*)(ylo + nf * 8) = __floats2half2_rn(oacc[nf][0] * ilo, oacc[nf][1] * ilo);
        *(__half2*)(yhi + nf * 8) = __floats2half2_rn(oacc[nf][2] * ihi, oacc[nf][3] * ihi);
    }
}

// ---------------------------------------------------------------------------
extern "C" void kernel_launch(void* const* d_in, const int* in_sizes, int n_in,
                              void* d_out, int out_size) {
    const float* x   = (const float*)d_in[0];
    const float* Wq  = (const float*)d_in[1];
    const float* bq  = (const float*)d_in[2];
    const float* Wk  = (const float*)d_in[3];
    const float* bk  = (const float*)d_in[4];
    const float* Wv  = (const float*)d_in[5];
    const float* bv  = (const float*)d_in[6];
    const float* Wp  = (const float*)d_in[7];
    const float* bp  = (const float*)d_in[8];
    const float* tbl = (const float*)d_in[9];
    float* out = (float*)d_out;

    cudaFuncSetAttribute(mma_qkv_kernel,
                         cudaFuncAttributeMaxDynamicSharedMemorySize, SMEM_TOTAL);
    cudaFuncSetAttribute(mma_proj_kernel,
                         cudaFuncAttributeMaxDynamicSharedMemorySize, SMEM_TOTAL);
    cudaFuncSetAttribute(attn_mma_kernel,
                         cudaFuncAttributeMaxDynamicSharedMemorySize, AT_SMEM);

    tables_kernel<<<(T_ * D_ + 255) / 256, 256>>>(tbl);
    convert_x_kernel<<<(B_ * T_ * C_ / 4) / 256, 256>>>(x);
    convert_w_kernel<<<dim3((C_ * C_ / 4) / 256, 4), 256>>>(Wq, Wk, Wv, Wp);

    mma_qkv_kernel<<<dim3(C_ / 128, (B_ * T_) / 128, 3), 512, SMEM_TOTAL>>>(bq, bk, bv);

    attn_mma_kernel<<<dim3(T_ / 64, B_ * H_), 128, AT_SMEM>>>();

    mma_proj_kernel<<<dim3(C_ / 128, (B_ * T_) / 128), 512, SMEM_TOTAL>>>(bp, out);
}

// round 11
// speedup vs baseline: 7.6621x; 1.0559x over previous
#include <cuda_runtime.h>
#include <cuda_fp16.h>
#include <math.h>
#include <math_constants.h>

#define B_  2
#define T_  2048
#define C_  1024
#define H_  16
#define D_  64
#define KCH 64               // GEMM K elems per pipeline chunk
#define NCH (C_ / KCH)       // 16 chunks

typedef unsigned int u32;

// ---------------------------------------------------------------------------
// Scratch (__device__ globals: allocation-free rule)
// ---------------------------------------------------------------------------
static __device__ __align__(16) float g_bias[H_*T_];
static __device__ __align__(16) float g_cos[T_*D_];
static __device__ __align__(16) float g_sin[T_*D_];
// fp16 operands
static __device__ __align__(16) __half g_xf[(size_t)B_*T_*C_];      // x fp16
static __device__ __align__(16) __half g_yf[(size_t)B_*T_*C_];      // attn out fp16
static __device__ __align__(16) __half g_w[4 * (size_t)C_*C_];      // weights fp16
// attention operands (head layout [B,H,T,D]), written by fused qkv epilogue
static __device__ __align__(16) __half g_qf[(size_t)B_*H_*T_*D_];
static __device__ __align__(16) __half g_kf[(size_t)B_*H_*T_*D_];
static __device__ __align__(16) __half g_vf[(size_t)B_*H_*T_*D_];

// ---------------------------------------------------------------------------
// Baseline-PTX helpers (sm_80-compatible: ldmatrix / mma.sync / cp.async)
// ---------------------------------------------------------------------------
__device__ __forceinline__ u32 smem_u32(const void* p) {
    u32 a;
    asm("{ .reg .u64 t; cvta.to.shared.u64 t, %1; cvt.u32.u64 %0, t; }" : "=r"(a) : "l"(p));
    return a;
}
__device__ __forceinline__ void ldsm_x4(u32 addr, u32& r0, u32& r1, u32& r2, u32& r3) {
    asm volatile("ldmatrix.sync.aligned.m8n8.x4.shared.b16 {%0,%1,%2,%3}, [%4];"
                 : "=r"(r0), "=r"(r1), "=r"(r2), "=r"(r3) : "r"(addr));
}
__device__ __forceinline__ void ldsm_x4_t(u32 addr, u32& r0, u32& r1, u32& r2, u32& r3) {
    asm volatile("ldmatrix.sync.aligned.m8n8.x4.trans.shared.b16 {%0,%1,%2,%3}, [%4];"
                 : "=r"(r0), "=r"(r1), "=r"(r2), "=r"(r3) : "r"(addr));
}
__device__ __forceinline__ void mma_f16(float* c, u32 a0, u32 a1, u32 a2, u32 a3,
                                        u32 b0, u32 b1) {
    asm volatile("mma.sync.aligned.m16n8k16.row.col.f32.f16.f16.f32 "
                 "{%0,%1,%2,%3}, {%4,%5,%6,%7}, {%8,%9}, {%0,%1,%2,%3};"
                 : "+f"(c[0]), "+f"(c[1]), "+f"(c[2]), "+f"(c[3])
                 : "r"(a0), "r"(a1), "r"(a2), "r"(a3), "r"(b0), "r"(b1));
}
#define CP_ASYNC16(dst, src) \
    asm volatile("cp.async.cg.shared.global [%0], [%1], 16;" :: "r"(dst), "l"(src))
#define CP_COMMIT() asm volatile("cp.async.commit_group;" ::: "memory")
#define CP_WAIT2()  asm volatile("cp.async.wait_group 2;" ::: "memory")
#define CP_WAIT1()  asm volatile("cp.async.wait_group 1;" ::: "memory")
#define CP_WAIT0()  asm volatile("cp.async.wait_group 0;" ::: "memory")

__device__ __forceinline__ u32 pack_f16(float lo, float hi) {
    __half2 h = __floats2half2_rn(lo, hi);
    return *(u32*)&h;
}

// ---------------------------------------------------------------------------
// Fused prep: convert x, convert W, build tables (one launch)
// blocks [0,4096): x ; [4096,8192): W ; [8192,8704): tables
// ---------------------------------------------------------------------------
__global__ void prep_kernel(const float* __restrict__ xin,
                            const float* __restrict__ Wq, const float* __restrict__ Wk,
                            const float* __restrict__ Wv, const float* __restrict__ Wp,
                            const float* __restrict__ rel_table) {
    int bx = blockIdx.x;
    int tid = threadIdx.x;
    if (bx < 4096) {
        int i = bx * 256 + tid;
        float4 v = ((const float4*)xin)[i];
        ((__half2*)g_xf)[i * 2 + 0] = __floats2half2_rn(v.x, v.y);
        ((__half2*)g_xf)[i * 2 + 1] = __floats2half2_rn(v.z, v.w);
    } else if (bx < 8192) {
        int bx2 = bx - 4096;
        int z = bx2 >> 10;
        const float* W = z == 0 ? Wq : z == 1 ? Wk : z == 2 ? Wv : Wp;
        __half* ow = g_w + (size_t)z * C_ * C_;
        int i = (bx2 & 1023) * 256 + tid;
        float4 v = ((const float4*)W)[i];
        ((__half2*)ow)[i * 2 + 0] = __floats2half2_rn(v.x, v.y);
        ((__half2*)ow)[i * 2 + 1] = __floats2half2_rn(v.z, v.w);
    } else {
        int idx = (bx - 8192) * 256 + tid;
        if (idx < T_ * D_) {
            int t = idx >> 6;
            int d = idx & 63;
            int j = d & 31;
            float inv = (float)pow(10000.0, -(double)(2 * j) / 64.0);
            float fr = (float)t * inv;
            g_cos[idx] = cosf(fr);
            g_sin[idx] = sinf(fr);
        }
        if (idx < H_ * T_) {
            int h = idx / T_;
            int n = idx % T_;
            int bucket;
            if (n < 16) {
                bucket = n;
            } else {
                float v = logf((float)n * (1.0f / 16.0f)) / 2.0794415416798357f * 16.0f;
                bucket = 16 + (int)v;
                if (bucket > 31) bucket = 31;
            }
            g_bias[idx] = rel_table[bucket * H_ + h];
        }
    }
}

// ---------------------------------------------------------------------------
// HMMA GEMM v6: A fp16 x W fp16, 4-stage cp.async pipeline (1 sync/chunk).
// 128x128 CTA, 512 threads (16 warps 4x4, warp tile 32x32), K chunks of 64.
// mode 0: proj (fp32 row-major out)
// mode 1: Q (rope + 1/8 -> g_qf fp16 head layout)   mode 2: K (rope -> g_kf)
// mode 3: V (direct fp16 -> g_vf)
// ---------------------------------------------------------------------------
#define SA 72        // A smem row stride (halves)
#define SB 136       // B smem row stride (halves)
#define A_OFF 0
#define B_OFF (128 * SA * 2)                      // 18432
#define STAGE_BYTES (B_OFF + KCH * SB * 2)        // 35840
#define SMEM_TOTAL (4 * STAGE_BYTES)              // 143360

__device__ __forceinline__ void hmma_gemm_body(
        const __half* __restrict__ Af, const __half* __restrict__ Wf,
        const float* __restrict__ bias, void* outp, int mode) {
    extern __shared__ char smem[];
    u32 sb = smem_u32(smem);

    int tid = threadIdx.x;
    int lane = tid & 31;
    int wid = tid >> 5;
    int wm = wid & 3;
    int wn = wid >> 2;
    int bm = blockIdx.y * 128;
    int bn = blockIdx.x * 128;

    float acc[2][4][4];
#pragma unroll
    for (int i = 0; i < 2; i++)
#pragma unroll
        for (int j = 0; j < 4; j++)
#pragma unroll
            for (int r = 0; r < 4; r++) acc[i][j][r] = 0.f;

    auto load_chunk = [&](int c, int s) {
        u32 st = sb + s * STAGE_BYTES;
        int c0 = c * KCH;
#pragma unroll
        for (int u = tid; u < 1024; u += 512) {
            int row = u >> 3, seg = u & 7;
            size_t gofs = (size_t)(bm + row) * C_ + c0 + seg * 8;
            CP_ASYNC16(st + A_OFF + (u32)(row * SA + seg * 8) * 2, Af + gofs);
        }
#pragma unroll
        for (int u = tid; u < 1024; u += 512) {
            int row = u >> 4, seg = u & 15;
            size_t gofs = (size_t)(c0 + row) * C_ + bn + seg * 8;
            CP_ASYNC16(st + B_OFF + (u32)(row * SB + seg * 8) * 2, Wf + gofs);
        }
        CP_COMMIT();
    };

    load_chunk(0, 0);
    load_chunk(1, 1);

    int lr = lane & 15;
    int lh = lane >> 4;

    for (int c = 0; c < NCH; c++) {
        if (c + 2 < NCH) load_chunk(c + 2, (c + 2) & 3);
        if (c < NCH - 2)      CP_WAIT2();
        else if (c < NCH - 1) CP_WAIT1();
        else                  CP_WAIT0();
        __syncthreads();

        u32 st = sb + (c & 3) * STAGE_BYTES;
#pragma unroll
        for (int ks = 0; ks < 4; ks++) {
            int k0 = ks * 16;
            u32 af[2][4];
#pragma unroll
            for (int mt = 0; mt < 2; mt++) {
                u32 arow = (u32)(wm * 32 + mt * 16 + lr);
                u32 aoff = (arow * SA + k0 + lh * 8) * 2;
                ldsm_x4(st + A_OFF + aoff, af[mt][0], af[mt][1], af[mt][2], af[mt][3]);
            }
#pragma unroll
            for (int np = 0; np < 2; np++) {
                u32 brow = (u32)(k0 + lr);
                u32 bcol = (u32)(wn * 32 + np * 16 + lh * 8);
                u32 boff = (brow * SB + bcol) * 2;
                u32 b0, b1, b2, b3;
                ldsm_x4_t(st + B_OFF + boff, b0, b1, b2, b3);
#pragma unroll
                for (int mt = 0; mt < 2; mt++) {
                    mma_f16(acc[mt][np * 2],     af[mt][0], af[mt][1], af[mt][2], af[mt][3], b0, b1);
                    mma_f16(acc[mt][np * 2 + 1], af[mt][0], af[mt][1], af[mt][2], af[mt][3], b2, b3);
                }
            }
        }
    }
    __syncthreads();

    int rq = lane >> 2;
    int cq = (lane & 3) * 2;

    if (mode == 0) {
        float* out = (float*)outp;
#pragma unroll
        for (int mt = 0; mt < 2; mt++)
#pragma unroll
            for (int nt = 0; nt < 4; nt++) {
                int gc = bn + wn * 32 + nt * 8 + cq;
                float b0 = bias[gc], b1 = bias[gc + 1];
#pragma unroll
                for (int half = 0; half < 2; half++) {
                    int grow = bm + wm * 32 + mt * 16 + rq + half * 8;
                    float2 o;
                    o.x = acc[mt][nt][half * 2 + 0] + b0;
                    o.y = acc[mt][nt][half * 2 + 1] + b1;
                    *(float2*)(out + (size_t)grow * C_ + gc) = o;
                }
            }
    } else if (mode == 3) {
        __half* out = (__half*)outp;
#pragma unroll
        for (int mt = 0; mt < 2; mt++)
#pragma unroll
            for (int nt = 0; nt < 4; nt++) {
                int gc = bn + wn * 32 + nt * 8 + cq;
                float b0 = bias[gc], b1 = bias[gc + 1];
                int h = gc >> 6, d0 = gc & 63;
#pragma unroll
                for (int half = 0; half < 2; half++) {
                    int grow = bm + wm * 32 + mt * 16 + rq + half * 8;
                    int b = grow >> 11, t = grow & (T_ - 1);
                    __half2 o = __floats2half2_rn(acc[mt][nt][half * 2 + 0] + b0,
                                                  acc[mt][nt][half * 2 + 1] + b1);
                    *(__half2*)(out + (((size_t)b * H_ + h) * T_ + t) * D_ + d0) = o;
                }
            }
    } else {
        // Q/K: stage fp32 tile in smem, rope pairs (d, d+32) -> fp16, vectorized x2
        float* cs = (float*)smem;
#pragma unroll
        for (int mt = 0; mt < 2; mt++)
#pragma unroll
            for (int nt = 0; nt < 4; nt++) {
                int lc = wn * 32 + nt * 8 + cq;
                int gc = bn + lc;
                float b0 = bias[gc], b1 = bias[gc + 1];
#pragma unroll
                for (int half = 0; half < 2; half++) {
                    int lrow = wm * 32 + mt * 16 + rq + half * 8;
                    cs[lrow * 132 + lc]     = acc[mt][nt][half * 2 + 0] + b0;
                    cs[lrow * 132 + lc + 1] = acc[mt][nt][half * 2 + 1] + b1;
                }
            }
        __syncthreads();

        __half* out = (__half*)outp;
        float qscale = (mode == 1) ? 0.125f : 1.0f;
#pragma unroll
        for (int u = tid; u < 4096; u += 512) {
            int r  = u >> 5;                 // row 0..127
            int pp = u & 31;
            int hh = pp >> 4;                // which 64-col head half
            int dd = (pp & 15) * 2;          // 0..30 even
            int c  = hh * 64 + dd;
            int gc = bn + c;
            int h = gc >> 6;
            int grow = bm + r;
            int b = grow >> 11, t = grow & (T_ - 1);
            float x1a = cs[r * 132 + c],      x1b = cs[r * 132 + c + 1];
            float x2a = cs[r * 132 + c + 32], x2b = cs[r * 132 + c + 33];
            float2 cv = *(const float2*)&g_cos[(t << 6) + dd];
            float2 sv = *(const float2*)&g_sin[(t << 6) + dd];
            __half2 ya = __floats2half2_rn((x1a * cv.x - x2a * sv.x) * qscale,
                                           (x1b * cv.y - x2b * sv.y) * qscale);
            __half2 yb = __floats2half2_rn((x2a * cv.x + x1a * sv.x) * qscale,
                                           (x2b * cv.y + x1b * sv.y) * qscale);
            __half* dp = out + (((size_t)b * H_ + h) * T_ + t) * D_ + dd;
            *(__half2*)dp        = ya;
            *(__half2*)(dp + 32) = yb;
        }
    }
}

__global__ __launch_bounds__(512, 1) void mma_qkv_kernel(
        const float* __restrict__ bq, const float* __restrict__ bk,
        const float* __restrict__ bv) {
    int z = blockIdx.z;
    const __half* Wf = g_w + (size_t)z * C_ * C_;
    const float* bias = z == 0 ? bq : z == 1 ? bk : bv;
    void* dst = z == 0 ? (void*)g_qf : z == 1 ? (void*)g_kf : (void*)g_vf;
    hmma_gemm_body(g_xf, Wf, bias, dst, z + 1);
}

__global__ __launch_bounds__(512, 1) void mma_proj_kernel(
        const float* __restrict__ bp, float* __restrict__ out) {
    hmma_gemm_body(g_yf, g_w + 3 * (size_t)C_ * C_, bp, out, 0);
}

// ---------------------------------------------------------------------------
// HMMA flash attention v5: 64 queries / CTA (4 warps), 4-stage KV pipeline
// (1 sync/block), QK 1-product, PV 1-product, fp16 output direct to g_yf.
// ---------------------------------------------------------------------------
#define AST 72
#define KV_ARRB (64 * AST * 2)               // 9216
#define KV_STAGEB (2 * KV_ARRB)              // 18432 (K, V)
#define AT_SMEM (4 * KV_STAGEB + T_ * 4)     // 81920

__global__ __launch_bounds__(128) void attn_mma_kernel() {
    extern __shared__ char asm_[];
    u32 sbase = smem_u32(asm_);
    float* sbias = (float*)(asm_ + 4 * KV_STAGEB);
    __half* sst = (__half*)asm_;

    int bh = blockIdx.y;
    int h = bh & (H_ - 1);
    int qb = gridDim.x - 1 - blockIdx.x;      // big-work CTAs first
    int q0 = qb * 64;
    int tid = threadIdx.x;
    int lane = tid & 31;
    int w = tid >> 5;                         // 0..3
    int qw = q0 + w * 16;

    const __half* qf = g_qf + ((size_t)bh * T_ + q0) * D_;
    size_t kvo = (size_t)bh * T_ * D_;

    {
        const float4* b4 = (const float4*)(g_bias + h * T_);
        for (int i = tid; i < T_ / 4; i += 128) {
            float4 v = b4[i];
            v.x *= 0.125f; v.y *= 0.125f; v.z *= 0.125f; v.w *= 0.125f;
            ((float4*)sbias)[i] = v;
        }
    }
    // stage Q (64x64 fp16) into stage-0 area
    for (int u = tid; u < 512; u += 128) {
        int row = u >> 3, seg = u & 7;
        *(uint4*)(sst + row * AST + seg * 8) =
            *(const uint4*)(qf + row * 64 + seg * 8);
    }
    __syncthreads();

    u32 qfr[4][4];
    {
        int lr = lane & 15, lh = lane >> 4;
#pragma unroll
        for (int kc = 0; kc < 4; kc++) {
            u32 off = (u32)((w * 16 + lr) * AST + kc * 16 + lh * 8) * 2;
            ldsm_x4(sbase + off, qfr[kc][0], qfr[kc][1], qfr[kc][2], qfr[kc][3]);
        }
    }
    __syncthreads();

    auto load_kv = [&](int blk, int s) {
        u32 st = sbase + s * KV_STAGEB;
        const __half* kf = g_kf + kvo + (size_t)blk * 64 * 64;
        const __half* vf = g_vf + kvo + (size_t)blk * 64 * 64;
#pragma unroll
        for (int u = tid; u < 512; u += 128) {
            int row = u >> 3, seg = u & 7;
            u32 doff = (u32)(row * AST + seg * 8) * 2;
            int goff = row * 64 + seg * 8;
            CP_ASYNC16(st + doff,           kf + goff);
            CP_ASYNC16(st + KV_ARRB + doff, vf + goff);
        }
        CP_COMMIT();
    };

    int nblk = qb + 1;
    load_kv(0, 0);
    if (nblk > 1) load_kv(1, 1);

    float mlo = -CUDART_INF_F, mhi = -CUDART_INF_F;
    float llo = 0.f, lhi = 0.f;
    float oacc[8][4];
#pragma unroll
    for (int i = 0; i < 8; i++)
#pragma unroll
        for (int j = 0; j < 4; j++) oacc[i][j] = 0.f;

    int rlo = qw + (lane >> 2);
    int rhi = rlo + 8;
    int cq = (lane & 3) * 2;

    for (int blk = 0; blk < nblk; blk++) {
        if (blk + 2 < nblk) load_kv(blk + 2, (blk + 2) & 3);
        if (blk < nblk - 2)      CP_WAIT2();
        else if (blk < nblk - 1) CP_WAIT1();
        else                     CP_WAIT0();
        __syncthreads();

        int j0 = blk * 64;
        {
            u32 st = sbase + (blk & 3) * KV_STAGEB;
            int lr = lane & 15, lh = lane >> 4;

            // S = Q K^T
            float sacc[8][4];
#pragma unroll
            for (int i = 0; i < 8; i++)
#pragma unroll
                for (int j = 0; j < 4; j++) sacc[i][j] = 0.f;
#pragma unroll
            for (int kg = 0; kg < 4; kg++) {
#pragma unroll
                for (int kc = 0; kc < 4; kc++) {
                    u32 off = (u32)((kg * 16 + lr) * AST + kc * 16 + lh * 8) * 2;
                    u32 k0, k1, k2, k3;
                    ldsm_x4(st + off, k0, k1, k2, k3);
                    mma_f16(sacc[2 * kg],     qfr[kc][0], qfr[kc][1], qfr[kc][2], qfr[kc][3], k0, k2);
                    mma_f16(sacc[2 * kg + 1], qfr[kc][0], qfr[kc][1], qfr[kc][2], qfr[kc][3], k1, k3);
                }
            }

            // bias + causal mask
#pragma unroll
            for (int nf = 0; nf < 8; nf++) {
                int jc = j0 + nf * 8 + cq;
                int d0 = rlo - jc;
                int d2 = rhi - jc;
                sacc[nf][0] = (d0 >= 0) ? sacc[nf][0] + sbias[d0]     : -CUDART_INF_F;
                sacc[nf][1] = (d0 >= 1) ? sacc[nf][1] + sbias[d0 - 1] : -CUDART_INF_F;
                sacc[nf][2] = (d2 >= 0) ? sacc[nf][2] + sbias[d2]     : -CUDART_INF_F;
                sacc[nf][3] = (d2 >= 1) ? sacc[nf][3] + sbias[d2 - 1] : -CUDART_INF_F;
            }

            // row max
            float bmlo = sacc[0][0], bmhi = sacc[0][2];
#pragma unroll
            for (int nf = 0; nf < 8; nf++) {
                bmlo = fmaxf(bmlo, fmaxf(sacc[nf][0], sacc[nf][1]));
                bmhi = fmaxf(bmhi, fmaxf(sacc[nf][2], sacc[nf][3]));
            }
            bmlo = fmaxf(bmlo, __shfl_xor_sync(0xffffffffu, bmlo, 1));
            bmlo = fmaxf(bmlo, __shfl_xor_sync(0xffffffffu, bmlo, 2));
            bmhi = fmaxf(bmhi, __shfl_xor_sync(0xffffffffu, bmhi, 1));
            bmhi = fmaxf(bmhi, __shfl_xor_sync(0xffffffffu, bmhi, 2));

            float nmlo = fmaxf(mlo, bmlo), nmhi = fmaxf(mhi, bmhi);
            float clo = __expf(mlo - nmlo), chi = __expf(mhi - nmhi);
            mlo = nmlo; mhi = nmhi;
            llo *= clo; lhi *= chi;
#pragma unroll
            for (int nf = 0; nf < 8; nf++) {
                oacc[nf][0] *= clo; oacc[nf][1] *= clo;
                oacc[nf][2] *= chi; oacc[nf][3] *= chi;
            }

            // exp -> P (fp16 fragments)
            u32 pf[4][4];
#pragma unroll
            for (int nf = 0; nf < 8; nf++) {
                float p0 = __expf(sacc[nf][0] - mlo);
                float p1 = __expf(sacc[nf][1] - mlo);
                float p2 = __expf(sacc[nf][2] - mhi);
                float p3 = __expf(sacc[nf][3] - mhi);
                llo += p0 + p1;
                lhi += p2 + p3;
                int kc = nf >> 1, half = nf & 1;
                pf[kc][half * 2 + 0] = pack_f16(p0, p1);
                pf[kc][half * 2 + 1] = pack_f16(p2, p3);
            }

            // O += P V
#pragma unroll
            for (int dg = 0; dg < 4; dg++) {
#pragma unroll
                for (int kc = 0; kc < 4; kc++) {
                    u32 off = (u32)((kc * 16 + lr) * AST + dg * 16 + lh * 8) * 2;
                    u32 v0, v1, v2, v3;
                    ldsm_x4_t(st + KV_ARRB + off, v0, v1, v2, v3);
                    mma_f16(oacc[2 * dg],     pf[kc][0], pf[kc][1], pf[kc][2], pf[kc][3], v0, v1);
                    mma_f16(oacc[2 * dg + 1], pf[kc][0], pf[kc][1], pf[kc][2], pf[kc][3], v2, v3);
                }
            }
        }
    }

    llo += __shfl_xor_sync(0xffffffffu, llo, 1);
    llo += __shfl_xor_sync(0xffffffffu, llo, 2);
    lhi += __shfl_xor_sync(0xffffffffu, lhi, 1);
    lhi += __shfl_xor_sync(0xffffffffu, lhi, 2);
    float ilo = 1.f / llo, ihi = 1.f / lhi;

    // write fp16 directly to proj input g_yf [B*T, C]
    int b = bh >> 4;
    __half* ylo = g_yf + ((size_t)b * T_ + rlo) * C_ + h * D_ + cq;
    __half* yhi = g_yf + ((size_t)b * T_ + rhi) * C_ + h * D_ + cq;
#pragma unroll
    for (int nf = 0; nf < 8; nf++) {
        *(__half2*)(ylo + nf * 8) = __floats2half2_rn(oacc[nf][0] * ilo, oacc[nf][1] * ilo);
        *(__half2*)(yhi + nf * 8) = __floats2half2_rn(oacc[nf][2] * ihi, oacc[nf][3] * ihi);
    }
}

// ---------------------------------------------------------------------------
extern "C" void kernel_launch(void* const* d_in, const int* in_sizes, int n_in,
                              void* d_out, int out_size) {
    const float* x   = (const float*)d_in[0];
    const float* Wq  = (const float*)d_in[1];
    const float* bq  = (const float*)d_in[2];
    const float* Wk  = (const float*)d_in[3];
    const float* bk  = (const float*)d_in[4];
    const float* Wv  = (const float*)d_in[5];
    const float* bv  = (const float*)d_in[6];
    const float* Wp  = (const float*)d_in[7];
    const float* bp  = (const float*)d_in[8];
    const float* tbl = (const float*)d_in[9];
    float* out = (float*)d_out;

    cudaFuncSetAttribute(mma_qkv_kernel,
                         cudaFuncAttributeMaxDynamicSharedMemorySize, SMEM_TOTAL);
    cudaFuncSetAttribute(mma_proj_kernel,
                         cudaFuncAttributeMaxDynamicSharedMemorySize, SMEM_TOTAL);
    cudaFuncSetAttribute(attn_mma_kernel,
                         cudaFuncAttributeMaxDynamicSharedMemorySize, AT_SMEM);

    prep_kernel<<<8704, 256>>>(x, Wq, Wk, Wv, Wp, tbl);

    mma_qkv_kernel<<<dim3(C_ / 128, (B_ * T_) / 128, 3), 512, SMEM_TOTAL>>>(bq, bk, bv);

    attn_mma_kernel<<<dim3(T_ / 64, B_ * H_), 128, AT_SMEM>>>();

    mma_proj_kernel<<<dim3(C_ / 128, (B_ * T_) / 128), 512, SMEM_TOTAL>>>(bp, out);
}